// round 13
// baseline (speedup 1.0000x reference)
#include <cuda_runtime.h>
#include <cuda_fp16.h>
#include <cstdint>

// ---------------- problem constants ----------------
#define BB 4
#define SS 1024
#define DD 1280
#define HH 20
#define DH 64
#define DF 5120
#define MM (BB*SS)          // 4096 rows
#define NQKV (3*DD)         // 3840

// ---------------- scratch (device globals) ----------------
__device__ __half g_Wqkv [(size_t)NQKV*DD];     // [N][K] fp16, Q rows pre-scaled
__device__ __half g_W1t  [(size_t)DF*DD];
__device__ __half g_W2t  [(size_t)DD*DF];
__device__ __half g_QKV16[(size_t)MM*NQKV];
__device__ float  g_x1   [MM*DD];
__device__ __half g_h0   [MM*DD];
__device__ __half g_h1   [(size_t)MM*DF];

__device__ __forceinline__ void mma_f16(float c[4], const uint32_t a[4], const uint32_t b[2]) {
    asm volatile(
        "mma.sync.aligned.m16n8k16.row.col.f32.f16.f16.f32 "
        "{%0,%1,%2,%3}, {%4,%5,%6,%7}, {%8,%9}, {%0,%1,%2,%3};\n"
        : "+f"(c[0]), "+f"(c[1]), "+f"(c[2]), "+f"(c[3])
        : "r"(a[0]), "r"(a[1]), "r"(a[2]), "r"(a[3]), "r"(b[0]), "r"(b[1]));
}

__device__ __forceinline__ uint32_t smem_u32(const void* p) {
    uint32_t a;
    asm("{ .reg .u64 t; cvta.to.shared.u64 t, %1; cvt.u32.u64 %0, t; }" : "=r"(a) : "l"(p));
    return a;
}

#define CP_ASYNC16(sm, gp) \
    asm volatile("cp.async.cg.shared.global [%0], [%1], 16;" :: "r"(sm), "l"(gp) : "memory")
#define CP_COMMIT() asm volatile("cp.async.commit_group;" ::: "memory")
#define CP_WAIT0()  asm volatile("cp.async.wait_group 0;" ::: "memory")

#define LDSM4(r0, r1, r2, r3, addr) \
    asm volatile("ldmatrix.sync.aligned.m8n8.x4.shared.b16 {%0,%1,%2,%3}, [%4];" \
                 : "=r"(r0), "=r"(r1), "=r"(r2), "=r"(r3) : "r"(addr))

#define LDSM_T4(r0, r1, r2, r3, addr) \
    asm volatile("ldmatrix.sync.aligned.m8n8.x4.trans.shared.b16 {%0,%1,%2,%3}, [%4];" \
                 : "=r"(r0), "=r"(r1), "=r"(r2), "=r"(r3) : "r"(addr))

// ============================================================================
// Prep kernels
// ============================================================================
// fused Wq/Wk/Wv transpose+convert (z selects source; Q rows scaled 1/8)
__global__ void thalf_qkv(const float* __restrict__ Wq, const float* __restrict__ Wk,
                          const float* __restrict__ Wv, __half* __restrict__ dst)
{
    __shared__ float s[32][33];
    const int tx = threadIdx.x, ty = threadIdx.y;
    const int n0 = blockIdx.x * 32, k0 = blockIdx.y * 32;
    const int z  = blockIdx.z;
    const float* src = (z == 0) ? Wq : (z == 1) ? Wk : Wv;
    const float scale = (z == 0) ? 0.125f : 1.0f;
    __half* d = dst + (size_t)z * DD * DD;
#pragma unroll
    for (int i = 0; i < 4; i++)
        s[ty + i * 8][tx] = src[(size_t)(k0 + ty + i * 8) * DD + n0 + tx];
    __syncthreads();
#pragma unroll
    for (int i = 0; i < 4; i++)
        d[(size_t)(n0 + ty + i * 8) * DD + k0 + tx] =
            __float2half_rn(s[tx][ty + i * 8] * scale);
}

// combined W1 & W2 transpose+convert. z=0: W1 [DD][DF]->W1t [DF][DD];
// z=1: W2 [DF][DD]->W2t [DD][DF]. Grid (160, 40, 2); z=1 swaps bx/by roles.
__global__ void thalf2(const float* __restrict__ W1, const float* __restrict__ W2,
                       __half* __restrict__ W1t, __half* __restrict__ W2t)
{
    __shared__ float s[32][33];
    const int tx = threadIdx.x, ty = threadIdx.y;
    const int z  = blockIdx.z;
    const float* src = z ? W2 : W1;
    __half* dst      = z ? W2t : W1t;
    const int K = z ? DF : DD;       // src row dim (contraction)
    const int N = z ? DD : DF;       // src col dim (output rows of dst)
    const int n0 = (z ? blockIdx.y : blockIdx.x) * 32;
    const int k0 = (z ? blockIdx.x : blockIdx.y) * 32;
#pragma unroll
    for (int i = 0; i < 4; i++)
        s[ty + i * 8][tx] = src[(size_t)(k0 + ty + i * 8) * N + n0 + tx];
    __syncthreads();
#pragma unroll
    for (int i = 0; i < 4; i++)
        dst[(size_t)(n0 + ty + i * 8) * K + k0 + tx] =
            __float2half_rn(s[tx][ty + i * 8]);
}

// ============================================================================
// FP16 GEMM (m16n8k16, fp32 accum), cp.async 2-stage, ldmatrix fragment loads.
// MODE 1: C16 = half(relu(AB+bias)); MODE 2: C = AB+bias+resid
// ============================================================================
#define HR 72
#define BH_ST (128*HR)
#define G16_SMEM(MT) (2*((MT)*HR + BH_ST)*2)

template <int MODE, int MTILE>
__global__ void __launch_bounds__(256, (MTILE == 128) ? 2 : 3)
gemm_f16(const __half* __restrict__ A, const __half* __restrict__ Bm,
         float* __restrict__ C, __half* __restrict__ C16, int M, int N, int K,
         const float* __restrict__ bias, const float* __restrict__ resid)
{
    constexpr int NI   = MTILE / 32;
    constexpr int PA   = MTILE / 32;
    constexpr int A_ST = MTILE * HR;
    constexpr int STG  = A_ST + BH_ST;

    extern __shared__ __half smh[];
    const uint32_t smb = smem_u32(smh);

    const int t    = threadIdx.x;
    const int lane = t & 31;
    const int w    = t >> 5;
    const int wm   = w & 1;
    const int wn   = w >> 1;
    const int g    = lane >> 2;
    const int tg   = lane & 3;
    const int m0   = blockIdx.y * MTILE;
    const int n0   = blockIdx.x * 128;

    const int ldr = t >> 3;
    const int ldc = (t & 7) * 8;
    const __half* Ag0 = A  + (size_t)(m0 + ldr) * K + ldc;
    const __half* Bg0 = Bm + (size_t)(n0 + ldr) * K + ldc;
    const uint32_t Asd = smb + (uint32_t)((ldr * HR + ldc) * 2);
    const uint32_t Bsd = smb + (uint32_t)((A_ST + ldr * HR + ldc) * 2);

    auto issue = [&](int kt, int buf) {
        const uint32_t bo = (uint32_t)(buf * STG * 2);
        const __half* Ag = Ag0 + kt * 64;
        const __half* Bg = Bg0 + kt * 64;
#pragma unroll
        for (int p = 0; p < PA; p++)
            CP_ASYNC16(Asd + bo + p * 32 * HR * 2, Ag + (size_t)p * 32 * K);
#pragma unroll
        for (int p = 0; p < 4; p++)
            CP_ASYNC16(Bsd + bo + p * 32 * HR * 2, Bg + (size_t)p * 32 * K);
        CP_COMMIT();
    };

    const int lm16 = lane & 15;
    const int lhi  = lane >> 4;
    const int lb8  = (lane >> 3) & 1;
    const int l8   = lane & 7;
    uint32_t aoff[NI], boff[2];
#pragma unroll
    for (int i = 0; i < NI; i++)
        aoff[i] = (uint32_t)(((wm * (MTILE / 2) + i * 16 + lm16) * HR + lhi * 8) * 2);
#pragma unroll
    for (int jp = 0; jp < 2; jp++)
        boff[jp] = (uint32_t)((A_ST + (wn * 32 + jp * 16 + lhi * 8 + l8) * HR + lb8 * 8) * 2);

    float acc[NI][4][4];
#pragma unroll
    for (int i = 0; i < NI; i++)
#pragma unroll
        for (int j = 0; j < 4; j++)
#pragma unroll
            for (int q = 0; q < 4; q++) acc[i][j][q] = 0.f;

    issue(0, 0);

    const int KT = K >> 6;
    for (int kt = 0; kt < KT; kt++) {
        CP_WAIT0();
        __syncthreads();
        if (kt + 1 < KT) issue(kt + 1, (kt + 1) & 1);

        const uint32_t bufb = smb + (uint32_t)((kt & 1) * STG * 2);
#pragma unroll
        for (int ks = 0; ks < 4; ks++) {
            const uint32_t cob = (uint32_t)(ks * 32);
            uint32_t af[NI][4], bf[4][2];
#pragma unroll
            for (int i = 0; i < NI; i++)
                LDSM4(af[i][0], af[i][1], af[i][2], af[i][3], bufb + aoff[i] + cob);
#pragma unroll
            for (int jp = 0; jp < 2; jp++)
                LDSM4(bf[2*jp][0], bf[2*jp][1], bf[2*jp+1][0], bf[2*jp+1][1],
                      bufb + boff[jp] + cob);
#pragma unroll
            for (int i = 0; i < NI; i++)
#pragma unroll
                for (int j = 0; j < 4; j++)
                    mma_f16(acc[i][j], af[i], bf[j]);
        }
        __syncthreads();
    }

    // ---------------- epilogue ----------------
    const int mrow = m0 + wm * (MTILE / 2);
    const int ncol = n0 + wn * 32;
#pragma unroll
    for (int j = 0; j < 4; j++) {
        const int colj = ncol + j * 8 + tg * 2;
        float2 bv = *(const float2*)(bias + colj);
#pragma unroll
        for (int i = 0; i < NI; i++) {
            const int r0 = mrow + i * 16 + g;
            float2 v0 = make_float2(acc[i][j][0], acc[i][j][1]);
            float2 v1 = make_float2(acc[i][j][2], acc[i][j][3]);
            if (MODE == 1) {
                __half2 h0 = __floats2half2_rn(fmaxf(v0.x + bv.x, 0.f), fmaxf(v0.y + bv.y, 0.f));
                __half2 h1 = __floats2half2_rn(fmaxf(v1.x + bv.x, 0.f), fmaxf(v1.y + bv.y, 0.f));
                *(__half2*)(C16 + (size_t)r0 * N + colj)       = h0;
                *(__half2*)(C16 + (size_t)(r0 + 8) * N + colj) = h1;
            } else {
                float2 r0v = *(const float2*)(resid + (size_t)r0 * N + colj);
                float2 r1v = *(const float2*)(resid + (size_t)(r0 + 8) * N + colj);
                v0.x += bv.x + r0v.x; v0.y += bv.y + r0v.y;
                v1.x += bv.x + r1v.x; v1.y += bv.y + r1v.y;
                *(float2*)(C + (size_t)r0 * N + colj)       = v0;
                *(float2*)(C + (size_t)(r0 + 8) * N + colj) = v1;
            }
        }
    }
}

// ============================================================================
// QKV GEMM: A is fp32 (x), converted to fp16 in the loader (register-staged
// LDG prefetch) — removes the separate to_half pass. MTILE=64, 2 CTAs/SM.
// C16 = half(A @ B^T), B fp16 [N][K] pre-transposed.
// ============================================================================
#define QKV_A_ST (64*HR)
#define QKV_STG  (QKV_A_ST + BH_ST)
#define QKV_SMEM (2*QKV_STG*2)

__global__ void __launch_bounds__(256, 2)
gemm_qkv(const float* __restrict__ A, const __half* __restrict__ Bm,
         __half* __restrict__ C16, int M, int N, int K)
{
    constexpr int NI = 2;
    extern __shared__ __half smh[];
    const uint32_t smb = smem_u32(smh);

    const int t    = threadIdx.x;
    const int lane = t & 31;
    const int w    = t >> 5;
    const int wm   = w & 1;
    const int wn   = w >> 1;
    const int g    = lane >> 2;
    const int tg   = lane & 3;
    const int m0   = blockIdx.y * 64;
    const int n0   = blockIdx.x * 128;

    // A loader: fp32 -> fp16, register staged. row=t>>4 (+16/pass), col=(t&15)*4
    const int arow = t >> 4;
    const int acol = (t & 15) * 4;
    const float* Ag0 = A + (size_t)(m0 + arow) * K + acol;
    const uint32_t AsD = smb + (uint32_t)((arow * HR + acol) * 2);

    // B loader: cp.async
    const int ldr = t >> 3;
    const int ldc = (t & 7) * 8;
    const __half* Bg0 = Bm + (size_t)(n0 + ldr) * K + ldc;
    const uint32_t Bsd = smb + (uint32_t)((QKV_A_ST + ldr * HR + ldc) * 2);

    float4 aR[4];
    auto ldgA = [&](int kt) {
#pragma unroll
        for (int p = 0; p < 4; p++)
            aR[p] = *(const float4*)(Ag0 + kt * 64 + (size_t)p * 16 * K);
    };
    auto stsA = [&](int buf) {
        const uint32_t bo = (uint32_t)(buf * QKV_STG * 2);
#pragma unroll
        for (int p = 0; p < 4; p++) {
            __half2 h0 = __floats2half2_rn(aR[p].x, aR[p].y);
            __half2 h1 = __floats2half2_rn(aR[p].z, aR[p].w);
            asm volatile("st.shared.v2.b32 [%0], {%1,%2};" ::
                "r"(AsD + bo + (uint32_t)(p * 16 * HR * 2)),
                "r"(*(uint32_t*)&h0), "r"(*(uint32_t*)&h1) : "memory");
        }
    };
    auto issueB = [&](int kt, int buf) {
        const uint32_t bo = (uint32_t)(buf * QKV_STG * 2);
        const __half* Bg = Bg0 + kt * 64;
#pragma unroll
        for (int p = 0; p < 4; p++)
            CP_ASYNC16(Bsd + bo + p * 32 * HR * 2, Bg + (size_t)p * 32 * K);
        CP_COMMIT();
    };

    // fragment addresses
    const int lm16 = lane & 15;
    const int lhi  = lane >> 4;
    const int lb8  = (lane >> 3) & 1;
    const int l8   = lane & 7;
    uint32_t aoff[NI], boff[2];
#pragma unroll
    for (int i = 0; i < NI; i++)
        aoff[i] = (uint32_t)(((wm * 32 + i * 16 + lm16) * HR + lhi * 8) * 2);
#pragma unroll
    for (int jp = 0; jp < 2; jp++)
        boff[jp] = (uint32_t)((QKV_A_ST + (wn * 32 + jp * 16 + lhi * 8 + l8) * HR + lb8 * 8) * 2);

    float acc[NI][4][4];
#pragma unroll
    for (int i = 0; i < NI; i++)
#pragma unroll
        for (int j = 0; j < 4; j++)
#pragma unroll
            for (int q = 0; q < 4; q++) acc[i][j][q] = 0.f;

    ldgA(0);
    issueB(0, 0);
    stsA(0);

    const int KT = K >> 6;
    for (int kt = 0; kt < KT; kt++) {
        CP_WAIT0();
        __syncthreads();
        if (kt + 1 < KT) {
            ldgA(kt + 1);
            issueB(kt + 1, (kt + 1) & 1);
        }

        const uint32_t bufb = smb + (uint32_t)((kt & 1) * QKV_STG * 2);
#pragma unroll
        for (int ks = 0; ks < 4; ks++) {
            const uint32_t cob = (uint32_t)(ks * 32);
            uint32_t af[NI][4], bf[4][2];
#pragma unroll
            for (int i = 0; i < NI; i++)
                LDSM4(af[i][0], af[i][1], af[i][2], af[i][3], bufb + aoff[i] + cob);
#pragma unroll
            for (int jp = 0; jp < 2; jp++)
                LDSM4(bf[2*jp][0], bf[2*jp][1], bf[2*jp+1][0], bf[2*jp+1][1],
                      bufb + boff[jp] + cob);
#pragma unroll
            for (int i = 0; i < NI; i++)
#pragma unroll
                for (int j = 0; j < 4; j++)
                    mma_f16(acc[i][j], af[i], bf[j]);
        }
        if (kt + 1 < KT) stsA((kt + 1) & 1);
        __syncthreads();
    }

    // ---------------- epilogue: C16 = half(acc) ----------------
    const int mrow = m0 + wm * 32;
    const int ncol = n0 + wn * 32;
#pragma unroll
    for (int j = 0; j < 4; j++) {
        const int colj = ncol + j * 8 + tg * 2;
#pragma unroll
        for (int i = 0; i < NI; i++) {
            const int r0 = mrow + i * 16 + g;
            *(__half2*)(C16 + (size_t)r0 * N + colj) =
                __floats2half2_rn(acc[i][j][0], acc[i][j][1]);
            *(__half2*)(C16 + (size_t)(r0 + 8) * N + colj) =
                __floats2half2_rn(acc[i][j][2], acc[i][j][3]);
        }
    }
}

// ============================================================================
// Flash attention v4 + ldmatrix Q/K loads (validated round 11).
// ============================================================================
#define HRA 72
#define KV_H (64*HRA)
#define OFF_KA (128*HRA)
#define OFF_VA (OFF_KA + 2*KV_H)
#define ATT_HALVES (OFF_VA + 2*KV_H)
#define ATT_SMEM_BYTES (ATT_HALVES*2)

__global__ void __launch_bounds__(256, 2)
attention_tc(const __half* __restrict__ QKV, const float* __restrict__ X,
             float* __restrict__ X1)
{
    extern __shared__ __half smh[];
    const uint32_t smb = smem_u32(smh);

    const int t    = threadIdx.x;
    const int lane = t & 31;
    const int w    = t >> 5;
    const int g    = lane >> 2;
    const int tg   = lane & 3;

    const int qb   = blockIdx.x * 128;
    const int h    = blockIdx.y;
    const int b    = blockIdx.z;
    const int brow = b * SS;

    const __half* Qg = QKV + (size_t)(brow + qb) * NQKV + h * DH;
    const int ldr = t >> 3;
    const int ldc = (t & 7) * 8;

    auto issueKV = [&](int kb, int buf) {
        const __half* Kg = QKV + (size_t)(brow + kb) * NQKV + DD     + h * DH;
        const __half* Vg = QKV + (size_t)(brow + kb) * NQKV + 2 * DD + h * DH;
        const uint32_t kd = smb + (uint32_t)((OFF_KA + buf * KV_H) * 2);
        const uint32_t vd = smb + (uint32_t)((OFF_VA + buf * KV_H) * 2);
#pragma unroll
        for (int p = 0; p < 2; p++) {
            int r = ldr + p * 32;
            CP_ASYNC16(kd + (uint32_t)((r * HRA + ldc) * 2), Kg + (size_t)r * NQKV + ldc);
            CP_ASYNC16(vd + (uint32_t)((r * HRA + ldc) * 2), Vg + (size_t)r * NQKV + ldc);
        }
        CP_COMMIT();
    };

#pragma unroll
    for (int p = 0; p < 4; p++) {
        int e = p * 256 + t;
        int r = e >> 3, c8 = (e & 7) * 8;
        CP_ASYNC16(smb + (uint32_t)((r * HRA + c8) * 2), Qg + (size_t)r * NQKV + c8);
    }
    issueKV(0, 0);

    const int r0 = w * 16 + g;
    const int r1 = r0 + 8;
    float m0 = -1e30f, m1 = -1e30f, l0 = 0.f, l1 = 0.f;
    float oacc[8][4];
#pragma unroll
    for (int i = 0; i < 8; i++)
#pragma unroll
        for (int q = 0; q < 4; q++) oacc[i][q] = 0.f;

    const int lm16 = lane & 15;
    const int lhi  = lane >> 4;
    const int lb8  = (lane >> 3) & 1;
    const int l8   = lane & 7;
    const uint32_t qoff = (uint32_t)(((w * 16 + lm16) * HRA + lhi * 8) * 2);
    uint32_t koff[4];
#pragma unroll
    for (int jp = 0; jp < 4; jp++)
        koff[jp] = (uint32_t)(((jp * 16 + lhi * 8 + l8) * HRA + lb8 * 8) * 2);
    const int sel = lane >> 3;
    const int vlo = ((sel & 1) * 8 + l8) * HRA + (sel >> 1) * 8;

    for (int kt = 0; kt < SS / 64; kt++) {
        CP_WAIT0();
        __syncthreads();
        if (kt + 1 < SS / 64) issueKV((kt + 1) * 64, (kt + 1) & 1);

        const uint32_t ksb = smb + (uint32_t)((OFF_KA + (kt & 1) * KV_H) * 2);
        const uint32_t vsb = smb + (uint32_t)((OFF_VA + (kt & 1) * KV_H) * 2);

        float sacc[8][4];
#pragma unroll
        for (int j = 0; j < 8; j++)
#pragma unroll
            for (int q = 0; q < 4; q++) sacc[j][q] = 0.f;

#pragma unroll
        for (int kc = 0; kc < 4; kc++) {
            const uint32_t cob = (uint32_t)(kc * 32);
            uint32_t af[4];
            LDSM4(af[0], af[1], af[2], af[3], smb + qoff + cob);
#pragma unroll
            for (int jp = 0; jp < 4; jp++) {
                uint32_t k0r, k1r, k2r, k3r;
                LDSM4(k0r, k1r, k2r, k3r, ksb + koff[jp] + cob);
                uint32_t bf0[2] = { k0r, k1r };
                uint32_t bf1[2] = { k2r, k3r };
                mma_f16(sacc[2*jp],     af, bf0);
                mma_f16(sacc[2*jp + 1], af, bf1);
            }
        }

        float pm0 = -1e30f, pm1 = -1e30f;
#pragma unroll
        for (int j = 0; j < 8; j++) {
            pm0 = fmaxf(pm0, fmaxf(sacc[j][0], sacc[j][1]));
            pm1 = fmaxf(pm1, fmaxf(sacc[j][2], sacc[j][3]));
        }
        pm0 = fmaxf(pm0, __shfl_xor_sync(0xffffffffu, pm0, 1));
        pm0 = fmaxf(pm0, __shfl_xor_sync(0xffffffffu, pm0, 2));
        pm1 = fmaxf(pm1, __shfl_xor_sync(0xffffffffu, pm1, 1));
        pm1 = fmaxf(pm1, __shfl_xor_sync(0xffffffffu, pm1, 2));

        const float mn0 = fmaxf(m0, pm0);
        const float mn1 = fmaxf(m1, pm1);
        const float al0 = __expf(m0 - mn0);
        const float al1 = __expf(m1 - mn1);
        m0 = mn0; m1 = mn1;

        uint32_t pf0[8], pf1[8];
        float rs0 = 0.f, rs1 = 0.f;
#pragma unroll
        for (int j = 0; j < 8; j++) {
            float p00 = __expf(sacc[j][0] - mn0);
            float p01 = __expf(sacc[j][1] - mn0);
            float p10 = __expf(sacc[j][2] - mn1);
            float p11 = __expf(sacc[j][3] - mn1);
            rs0 += p00 + p01;
            rs1 += p10 + p11;
            __half2 h0 = __floats2half2_rn(p00, p01);
            __half2 h1 = __floats2half2_rn(p10, p11);
            pf0[j] = *(uint32_t*)&h0;
            pf1[j] = *(uint32_t*)&h1;
        }
        rs0 += __shfl_xor_sync(0xffffffffu, rs0, 1);
        rs0 += __shfl_xor_sync(0xffffffffu, rs0, 2);
        rs1 += __shfl_xor_sync(0xffffffffu, rs1, 1);
        rs1 += __shfl_xor_sync(0xffffffffu, rs1, 2);
        l0 = l0 * al0 + rs0;
        l1 = l1 * al1 + rs1;
#pragma unroll
        for (int i = 0; i < 8; i++) {
            oacc[i][0] *= al0; oacc[i][1] *= al0;
            oacc[i][2] *= al1; oacc[i][3] *= al1;
        }

#pragma unroll
        for (int kc = 0; kc < 4; kc++) {
            uint32_t af[4];
            af[0] = pf0[2 * kc];
            af[1] = pf1[2 * kc];
            af[2] = pf0[2 * kc + 1];
            af[3] = pf1[2 * kc + 1];
#pragma unroll
            for (int jp = 0; jp < 4; jp++) {
                uint32_t q0, q1, q2, q3;
                const uint32_t va = vsb +
                    (uint32_t)((kc * 16 * HRA + jp * 16 + vlo) * 2);
                LDSM_T4(q0, q1, q2, q3, va);
                uint32_t bf0[2] = { q0, q1 };
                uint32_t bf1[2] = { q2, q3 };
                mma_f16(oacc[jp * 2],     af, bf0);
                mma_f16(oacc[jp * 2 + 1], af, bf1);
            }
        }
    }

    const float il0 = 1.f / l0;
    const float il1 = 1.f / l1;
    const size_t tok0 = (size_t)(brow + qb + r0);
    const size_t tok1 = (size_t)(brow + qb + r1);
#pragma unroll
    for (int jd = 0; jd < 8; jd++) {
        const int col = h * DH + jd * 8 + tg * 2;
        float2 x0 = *(const float2*)(X + tok0 * DD + col);
        float2 x1 = *(const float2*)(X + tok1 * DD + col);
        float2 o0 = make_float2(oacc[jd][0] * il0 + x0.x, oacc[jd][1] * il0 + x0.y);
        float2 o1 = make_float2(oacc[jd][2] * il1 + x1.x, oacc[jd][3] * il1 + x1.y);
        *(float2*)(X1 + tok0 * DD + col) = o0;
        *(float2*)(X1 + tok1 * DD + col) = o1;
    }
}

// ============================================================================
// LayerNorm over D=1280; emits fp16 for the FFN1 GEMM.
// ============================================================================
__global__ void __launch_bounds__(256)
ln_kernel(const float* __restrict__ X, const float* __restrict__ gam,
          const float* __restrict__ bet, __half* __restrict__ Y)
{
    const int row = blockIdx.x;
    const float* xr = X + (size_t)row * DD;
    float v[5];
    float sum = 0.f, sq = 0.f;
#pragma unroll
    for (int i = 0; i < 5; i++) {
        v[i] = xr[threadIdx.x + i * 256];
        sum += v[i];
        sq  += v[i] * v[i];
    }
#pragma unroll
    for (int off = 16; off; off >>= 1) {
        sum += __shfl_xor_sync(0xffffffffu, sum, off);
        sq  += __shfl_xor_sync(0xffffffffu, sq , off);
    }
    __shared__ float sS[8], sQ[8];
    const int w = threadIdx.x >> 5, lane = threadIdx.x & 31;
    if (lane == 0) { sS[w] = sum; sQ[w] = sq; }
    __syncthreads();
    if (threadIdx.x == 0) {
        float a = 0.f, q = 0.f;
#pragma unroll
        for (int i = 0; i < 8; i++) { a += sS[i]; q += sQ[i]; }
        sS[0] = a; sQ[0] = q;
    }
    __syncthreads();
    const float mu   = sS[0] * (1.0f / DD);
    const float var  = sQ[0] * (1.0f / DD) - mu * mu;
    const float rstd = rsqrtf(var + 1e-5f);
    __half* yr = Y + (size_t)row * DD;
#pragma unroll
    for (int i = 0; i < 5; i++) {
        int c = threadIdx.x + i * 256;
        yr[c] = __float2half_rn((v[i] - mu) * rstd * gam[c] + bet[c]);
    }
}

// ============================================================================
// launch (single stream — graph-capture safe, no stream/event allocations)
// ============================================================================
extern "C" void kernel_launch(void* const* d_in, const int* in_sizes, int n_in,
                              void* d_out, int out_size)
{
    const float* x   = (const float*)d_in[0];
    const float* Wq  = (const float*)d_in[1];
    const float* Wk  = (const float*)d_in[2];
    const float* Wv  = (const float*)d_in[3];
    const float* lng = (const float*)d_in[4];
    const float* lnb = (const float*)d_in[5];
    const float* W1  = (const float*)d_in[6];
    const float* b1  = (const float*)d_in[7];
    const float* W2  = (const float*)d_in[8];
    const float* b2  = (const float*)d_in[9];
    float* out = (float*)d_out;

    __half *Wqkv, *W1t, *W2t, *QKV16, *H0, *H1;
    float *X1;
    cudaGetSymbolAddress((void**)&Wqkv,  g_Wqkv);
    cudaGetSymbolAddress((void**)&W1t,   g_W1t);
    cudaGetSymbolAddress((void**)&W2t,   g_W2t);
    cudaGetSymbolAddress((void**)&QKV16, g_QKV16);
    cudaGetSymbolAddress((void**)&X1,    g_x1);
    cudaGetSymbolAddress((void**)&H0,    g_h0);
    cudaGetSymbolAddress((void**)&H1,    g_h1);

    cudaFuncSetAttribute((const void*)gemm_qkv,        cudaFuncAttributeMaxDynamicSharedMemorySize, QKV_SMEM);
    cudaFuncSetAttribute((const void*)gemm_f16<1,128>, cudaFuncAttributeMaxDynamicSharedMemorySize, G16_SMEM(128));
    cudaFuncSetAttribute((const void*)gemm_f16<2,128>, cudaFuncAttributeMaxDynamicSharedMemorySize, G16_SMEM(128));
    cudaFuncSetAttribute((const void*)attention_tc,    cudaFuncAttributeMaxDynamicSharedMemorySize, ATT_SMEM_BYTES);

    const dim3 blk(256);
    const dim3 tb(32, 8);

    // prep: weight transposes (x conversion is fused into gemm_qkv)
    thalf_qkv<<<dim3(DD/32, DD/32, 3), tb>>>(Wq, Wk, Wv, Wqkv);
    thalf2<<<dim3(DF/32, DD/32, 2), tb>>>(W1, W2, W1t, W2t);

    // QKV projection (fp32 A converted in-kernel) -> fp16
    gemm_qkv<<<dim3(NQKV/128, MM/64), blk, QKV_SMEM>>>(
        x, Wqkv, QKV16, MM, NQKV, DD);

    // fused fp16 attention + residual
    attention_tc<<<dim3(SS/128, HH, BB), blk, ATT_SMEM_BYTES>>>(QKV16, x, X1);

    // layernorm -> fp16
    ln_kernel<<<MM, 256>>>(X1, lng, lnb, H0);

    // FFN
    gemm_f16<1,128><<<dim3(DF/128, MM/128), blk, G16_SMEM(128)>>>(
        H0, W1t, nullptr, H1, MM, DF, DD, b1, nullptr);
    gemm_f16<2,128><<<dim3(DD/128, MM/128), blk, G16_SMEM(128)>>>(
        H1, W2t, out, nullptr, MM, DD, DF, b2, X1);
}

// round 14
// speedup vs baseline: 1.0476x; 1.0476x over previous
#include <cuda_runtime.h>
#include <cuda_fp16.h>
#include <cstdint>

// ---------------- problem constants ----------------
#define BB 4
#define SS 1024
#define DD 1280
#define HH 20
#define DH 64
#define DF 5120
#define MM (BB*SS)          // 4096 rows
#define NQKV (3*DD)         // 3840

// ---------------- scratch (device globals) ----------------
__device__ __half g_x16  [(size_t)MM*DD];
__device__ __half g_Wqkv [(size_t)NQKV*DD];     // [N][K] fp16, Q rows pre-scaled
__device__ __half g_W1t  [(size_t)DF*DD];
__device__ __half g_W2t  [(size_t)DD*DF];
__device__ __half g_QKV16[(size_t)MM*NQKV];
__device__ float  g_x1   [MM*DD];
__device__ __half g_h0   [MM*DD];
__device__ __half g_h1   [(size_t)MM*DF];

__device__ __forceinline__ void mma_f16(float c[4], const uint32_t a[4], const uint32_t b[2]) {
    asm volatile(
        "mma.sync.aligned.m16n8k16.row.col.f32.f16.f16.f32 "
        "{%0,%1,%2,%3}, {%4,%5,%6,%7}, {%8,%9}, {%0,%1,%2,%3};\n"
        : "+f"(c[0]), "+f"(c[1]), "+f"(c[2]), "+f"(c[3])
        : "r"(a[0]), "r"(a[1]), "r"(a[2]), "r"(a[3]), "r"(b[0]), "r"(b[1]));
}

__device__ __forceinline__ uint32_t smem_u32(const void* p) {
    uint32_t a;
    asm("{ .reg .u64 t; cvta.to.shared.u64 t, %1; cvt.u32.u64 %0, t; }" : "=r"(a) : "l"(p));
    return a;
}

#define CP_ASYNC16(sm, gp) \
    asm volatile("cp.async.cg.shared.global [%0], [%1], 16;" :: "r"(sm), "l"(gp) : "memory")
#define CP_COMMIT() asm volatile("cp.async.commit_group;" ::: "memory")
#define CP_WAIT0()  asm volatile("cp.async.wait_group 0;" ::: "memory")

#define LDSM4(r0, r1, r2, r3, addr) \
    asm volatile("ldmatrix.sync.aligned.m8n8.x4.shared.b16 {%0,%1,%2,%3}, [%4];" \
                 : "=r"(r0), "=r"(r1), "=r"(r2), "=r"(r3) : "r"(addr))

#define LDSM_T4(r0, r1, r2, r3, addr) \
    asm volatile("ldmatrix.sync.aligned.m8n8.x4.trans.shared.b16 {%0,%1,%2,%3}, [%4];" \
                 : "=r"(r0), "=r"(r1), "=r"(r2), "=r"(r3) : "r"(addr))

// ============================================================================
// Prep kernels
// ============================================================================
__global__ void to_half(const float* __restrict__ in, __half* __restrict__ out, int n4)
{
    int i = blockIdx.x * 256 + threadIdx.x;
    if (i >= n4) return;
    float4 v = ((const float4*)in)[i];
    ((__half2*)out)[i * 2]     = __floats2half2_rn(v.x, v.y);
    ((__half2*)out)[i * 2 + 1] = __floats2half2_rn(v.z, v.w);
}

// fused Wq/Wk/Wv transpose+convert (z selects source; Q rows scaled 1/8)
__global__ void thalf_qkv(const float* __restrict__ Wq, const float* __restrict__ Wk,
                          const float* __restrict__ Wv, __half* __restrict__ dst)
{
    __shared__ float s[32][33];
    const int tx = threadIdx.x, ty = threadIdx.y;
    const int n0 = blockIdx.x * 32, k0 = blockIdx.y * 32;
    const int z  = blockIdx.z;
    const float* src = (z == 0) ? Wq : (z == 1) ? Wk : Wv;
    const float scale = (z == 0) ? 0.125f : 1.0f;
    __half* d = dst + (size_t)z * DD * DD;
#pragma unroll
    for (int i = 0; i < 4; i++)
        s[ty + i * 8][tx] = src[(size_t)(k0 + ty + i * 8) * DD + n0 + tx];
    __syncthreads();
#pragma unroll
    for (int i = 0; i < 4; i++)
        d[(size_t)(n0 + ty + i * 8) * DD + k0 + tx] =
            __float2half_rn(s[tx][ty + i * 8] * scale);
}

// combined W1 & W2 transpose+convert. z=0: W1 [DD][DF]->W1t [DF][DD];
// z=1: W2 [DF][DD]->W2t [DD][DF]. Grid (160, 40, 2); z=1 swaps bx/by roles.
__global__ void thalf2(const float* __restrict__ W1, const float* __restrict__ W2,
                       __half* __restrict__ W1t, __half* __restrict__ W2t)
{
    __shared__ float s[32][33];
    const int tx = threadIdx.x, ty = threadIdx.y;
    const int z  = blockIdx.z;
    const float* src = z ? W2 : W1;
    __half* dst      = z ? W2t : W1t;
    const int K = z ? DF : DD;       // dst inner (contraction) dim
    const int N = z ? DD : DF;       // src col dim
    const int n0 = (z ? blockIdx.y : blockIdx.x) * 32;
    const int k0 = (z ? blockIdx.x : blockIdx.y) * 32;
#pragma unroll
    for (int i = 0; i < 4; i++)
        s[ty + i * 8][tx] = src[(size_t)(k0 + ty + i * 8) * N + n0 + tx];
    __syncthreads();
#pragma unroll
    for (int i = 0; i < 4; i++)
        dst[(size_t)(n0 + ty + i * 8) * K + k0 + tx] =
            __float2half_rn(s[tx][ty + i * 8]);
}

// ============================================================================
// FP16 GEMM (m16n8k16, fp32 accum), cp.async 2-stage, ldmatrix fragment loads.
// MODE 0: C16 = half(AB); MODE 1: C16 = half(relu(AB+bias)); MODE 2: C = AB+bias+resid
// ============================================================================
#define HR 72
#define BH_ST (128*HR)
#define G16_SMEM(MT) (2*((MT)*HR + BH_ST)*2)

template <int MODE, int MTILE>
__global__ void __launch_bounds__(256, (MTILE == 128) ? 2 : 3)
gemm_f16(const __half* __restrict__ A, const __half* __restrict__ Bm,
         float* __restrict__ C, __half* __restrict__ C16, int M, int N, int K,
         const float* __restrict__ bias, const float* __restrict__ resid)
{
    constexpr int NI   = MTILE / 32;
    constexpr int PA   = MTILE / 32;
    constexpr int A_ST = MTILE * HR;
    constexpr int STG  = A_ST + BH_ST;

    extern __shared__ __half smh[];
    const uint32_t smb = smem_u32(smh);

    const int t    = threadIdx.x;
    const int lane = t & 31;
    const int w    = t >> 5;
    const int wm   = w & 1;
    const int wn   = w >> 1;
    const int g    = lane >> 2;
    const int tg   = lane & 3;
    const int m0   = blockIdx.y * MTILE;
    const int n0   = blockIdx.x * 128;

    const int ldr = t >> 3;
    const int ldc = (t & 7) * 8;
    const __half* Ag0 = A  + (size_t)(m0 + ldr) * K + ldc;
    const __half* Bg0 = Bm + (size_t)(n0 + ldr) * K + ldc;
    const uint32_t Asd = smb + (uint32_t)((ldr * HR + ldc) * 2);
    const uint32_t Bsd = smb + (uint32_t)((A_ST + ldr * HR + ldc) * 2);

    auto issue = [&](int kt, int buf) {
        const uint32_t bo = (uint32_t)(buf * STG * 2);
        const __half* Ag = Ag0 + kt * 64;
        const __half* Bg = Bg0 + kt * 64;
#pragma unroll
        for (int p = 0; p < PA; p++)
            CP_ASYNC16(Asd + bo + p * 32 * HR * 2, Ag + (size_t)p * 32 * K);
#pragma unroll
        for (int p = 0; p < 4; p++)
            CP_ASYNC16(Bsd + bo + p * 32 * HR * 2, Bg + (size_t)p * 32 * K);
        CP_COMMIT();
    };

    // ldmatrix per-lane fragment addresses
    const int lm16 = lane & 15;
    const int lhi  = lane >> 4;
    const int lb8  = (lane >> 3) & 1;
    const int l8   = lane & 7;
    uint32_t aoff[NI], boff[2];
#pragma unroll
    for (int i = 0; i < NI; i++)
        aoff[i] = (uint32_t)(((wm * (MTILE / 2) + i * 16 + lm16) * HR + lhi * 8) * 2);
#pragma unroll
    for (int jp = 0; jp < 2; jp++)
        boff[jp] = (uint32_t)((A_ST + (wn * 32 + jp * 16 + lhi * 8 + l8) * HR + lb8 * 8) * 2);

    float acc[NI][4][4];
#pragma unroll
    for (int i = 0; i < NI; i++)
#pragma unroll
        for (int j = 0; j < 4; j++)
#pragma unroll
            for (int q = 0; q < 4; q++) acc[i][j][q] = 0.f;

    issue(0, 0);

    const int KT = K >> 6;
    for (int kt = 0; kt < KT; kt++) {
        CP_WAIT0();
        __syncthreads();
        if (kt + 1 < KT) issue(kt + 1, (kt + 1) & 1);

        const uint32_t bufb = smb + (uint32_t)((kt & 1) * STG * 2);
#pragma unroll
        for (int ks = 0; ks < 4; ks++) {
            const uint32_t cob = (uint32_t)(ks * 32);
            uint32_t af[NI][4], bf[4][2];
#pragma unroll
            for (int i = 0; i < NI; i++)
                LDSM4(af[i][0], af[i][1], af[i][2], af[i][3], bufb + aoff[i] + cob);
#pragma unroll
            for (int jp = 0; jp < 2; jp++)
                LDSM4(bf[2*jp][0], bf[2*jp][1], bf[2*jp+1][0], bf[2*jp+1][1],
                      bufb + boff[jp] + cob);
#pragma unroll
            for (int i = 0; i < NI; i++)
#pragma unroll
                for (int j = 0; j < 4; j++)
                    mma_f16(acc[i][j], af[i], bf[j]);
        }
        __syncthreads();
    }

    // ---------------- epilogue ----------------
    const int mrow = m0 + wm * (MTILE / 2);
    const int ncol = n0 + wn * 32;
#pragma unroll
    for (int j = 0; j < 4; j++) {
        const int colj = ncol + j * 8 + tg * 2;
        float2 bv = make_float2(0.f, 0.f);
        if (MODE == 1 || MODE == 2) bv = *(const float2*)(bias + colj);
#pragma unroll
        for (int i = 0; i < NI; i++) {
            const int r0 = mrow + i * 16 + g;
            float2 v0 = make_float2(acc[i][j][0], acc[i][j][1]);
            float2 v1 = make_float2(acc[i][j][2], acc[i][j][3]);
            if (MODE == 0) {
                *(__half2*)(C16 + (size_t)r0 * N + colj)       = __floats2half2_rn(v0.x, v0.y);
                *(__half2*)(C16 + (size_t)(r0 + 8) * N + colj) = __floats2half2_rn(v1.x, v1.y);
            } else if (MODE == 1) {
                __half2 h0 = __floats2half2_rn(fmaxf(v0.x + bv.x, 0.f), fmaxf(v0.y + bv.y, 0.f));
                __half2 h1 = __floats2half2_rn(fmaxf(v1.x + bv.x, 0.f), fmaxf(v1.y + bv.y, 0.f));
                *(__half2*)(C16 + (size_t)r0 * N + colj)       = h0;
                *(__half2*)(C16 + (size_t)(r0 + 8) * N + colj) = h1;
            } else {
                float2 r0v = *(const float2*)(resid + (size_t)r0 * N + colj);
                float2 r1v = *(const float2*)(resid + (size_t)(r0 + 8) * N + colj);
                v0.x += bv.x + r0v.x; v0.y += bv.y + r0v.y;
                v1.x += bv.x + r1v.x; v1.y += bv.y + r1v.y;
                *(float2*)(C + (size_t)r0 * N + colj)       = v0;
                *(float2*)(C + (size_t)(r0 + 8) * N + colj) = v1;
            }
        }
    }
}

// ============================================================================
// Flash attention v4 + ldmatrix Q/K loads (validated round 11).
// ============================================================================
#define HRA 72
#define KV_H (64*HRA)
#define OFF_KA (128*HRA)
#define OFF_VA (OFF_KA + 2*KV_H)
#define ATT_HALVES (OFF_VA + 2*KV_H)
#define ATT_SMEM_BYTES (ATT_HALVES*2)

__global__ void __launch_bounds__(256, 2)
attention_tc(const __half* __restrict__ QKV, const float* __restrict__ X,
             float* __restrict__ X1)
{
    extern __shared__ __half smh[];
    const uint32_t smb = smem_u32(smh);

    const int t    = threadIdx.x;
    const int lane = t & 31;
    const int w    = t >> 5;
    const int g    = lane >> 2;
    const int tg   = lane & 3;

    const int qb   = blockIdx.x * 128;
    const int h    = blockIdx.y;
    const int b    = blockIdx.z;
    const int brow = b * SS;

    const __half* Qg = QKV + (size_t)(brow + qb) * NQKV + h * DH;
    const int ldr = t >> 3;
    const int ldc = (t & 7) * 8;

    auto issueKV = [&](int kb, int buf) {
        const __half* Kg = QKV + (size_t)(brow + kb) * NQKV + DD     + h * DH;
        const __half* Vg = QKV + (size_t)(brow + kb) * NQKV + 2 * DD + h * DH;
        const uint32_t kd = smb + (uint32_t)((OFF_KA + buf * KV_H) * 2);
        const uint32_t vd = smb + (uint32_t)((OFF_VA + buf * KV_H) * 2);
#pragma unroll
        for (int p = 0; p < 2; p++) {
            int r = ldr + p * 32;
            CP_ASYNC16(kd + (uint32_t)((r * HRA + ldc) * 2), Kg + (size_t)r * NQKV + ldc);
            CP_ASYNC16(vd + (uint32_t)((r * HRA + ldc) * 2), Vg + (size_t)r * NQKV + ldc);
        }
        CP_COMMIT();
    };

#pragma unroll
    for (int p = 0; p < 4; p++) {
        int e = p * 256 + t;
        int r = e >> 3, c8 = (e & 7) * 8;
        CP_ASYNC16(smb + (uint32_t)((r * HRA + c8) * 2), Qg + (size_t)r * NQKV + c8);
    }
    issueKV(0, 0);

    const int r0 = w * 16 + g;
    const int r1 = r0 + 8;
    float m0 = -1e30f, m1 = -1e30f, l0 = 0.f, l1 = 0.f;
    float oacc[8][4];
#pragma unroll
    for (int i = 0; i < 8; i++)
#pragma unroll
        for (int q = 0; q < 4; q++) oacc[i][q] = 0.f;

    const int lm16 = lane & 15;
    const int lhi  = lane >> 4;
    const int lb8  = (lane >> 3) & 1;
    const int l8   = lane & 7;
    const uint32_t qoff = (uint32_t)(((w * 16 + lm16) * HRA + lhi * 8) * 2);
    uint32_t koff[4];
#pragma unroll
    for (int jp = 0; jp < 4; jp++)
        koff[jp] = (uint32_t)(((jp * 16 + lhi * 8 + l8) * HRA + lb8 * 8) * 2);
    const int sel = lane >> 3;
    const int vlo = ((sel & 1) * 8 + l8) * HRA + (sel >> 1) * 8;

    for (int kt = 0; kt < SS / 64; kt++) {
        CP_WAIT0();
        __syncthreads();
        if (kt + 1 < SS / 64) issueKV((kt + 1) * 64, (kt + 1) & 1);

        const uint32_t ksb = smb + (uint32_t)((OFF_KA + (kt & 1) * KV_H) * 2);
        const uint32_t vsb = smb + (uint32_t)((OFF_VA + (kt & 1) * KV_H) * 2);

        float sacc[8][4];
#pragma unroll
        for (int j = 0; j < 8; j++)
#pragma unroll
            for (int q = 0; q < 4; q++) sacc[j][q] = 0.f;

#pragma unroll
        for (int kc = 0; kc < 4; kc++) {
            const uint32_t cob = (uint32_t)(kc * 32);
            uint32_t af[4];
            LDSM4(af[0], af[1], af[2], af[3], smb + qoff + cob);
#pragma unroll
            for (int jp = 0; jp < 4; jp++) {
                uint32_t k0r, k1r, k2r, k3r;
                LDSM4(k0r, k1r, k2r, k3r, ksb + koff[jp] + cob);
                uint32_t bf0[2] = { k0r, k1r };
                uint32_t bf1[2] = { k2r, k3r };
                mma_f16(sacc[2*jp],     af, bf0);
                mma_f16(sacc[2*jp + 1], af, bf1);
            }
        }

        float pm0 = -1e30f, pm1 = -1e30f;
#pragma unroll
        for (int j = 0; j < 8; j++) {
            pm0 = fmaxf(pm0, fmaxf(sacc[j][0], sacc[j][1]));
            pm1 = fmaxf(pm1, fmaxf(sacc[j][2], sacc[j][3]));
        }
        pm0 = fmaxf(pm0, __shfl_xor_sync(0xffffffffu, pm0, 1));
        pm0 = fmaxf(pm0, __shfl_xor_sync(0xffffffffu, pm0, 2));
        pm1 = fmaxf(pm1, __shfl_xor_sync(0xffffffffu, pm1, 1));
        pm1 = fmaxf(pm1, __shfl_xor_sync(0xffffffffu, pm1, 2));

        const float mn0 = fmaxf(m0, pm0);
        const float mn1 = fmaxf(m1, pm1);
        const float al0 = __expf(m0 - mn0);
        const float al1 = __expf(m1 - mn1);
        m0 = mn0; m1 = mn1;

        uint32_t pf0[8], pf1[8];
        float rs0 = 0.f, rs1 = 0.f;
#pragma unroll
        for (int j = 0; j < 8; j++) {
            float p00 = __expf(sacc[j][0] - mn0);
            float p01 = __expf(sacc[j][1] - mn0);
            float p10 = __expf(sacc[j][2] - mn1);
            float p11 = __expf(sacc[j][3] - mn1);
            rs0 += p00 + p01;
            rs1 += p10 + p11;
            __half2 h0 = __floats2half2_rn(p00, p01);
            __half2 h1 = __floats2half2_rn(p10, p11);
            pf0[j] = *(uint32_t*)&h0;
            pf1[j] = *(uint32_t*)&h1;
        }
        rs0 += __shfl_xor_sync(0xffffffffu, rs0, 1);
        rs0 += __shfl_xor_sync(0xffffffffu, rs0, 2);
        rs1 += __shfl_xor_sync(0xffffffffu, rs1, 1);
        rs1 += __shfl_xor_sync(0xffffffffu, rs1, 2);
        l0 = l0 * al0 + rs0;
        l1 = l1 * al1 + rs1;
#pragma unroll
        for (int i = 0; i < 8; i++) {
            oacc[i][0] *= al0; oacc[i][1] *= al0;
            oacc[i][2] *= al1; oacc[i][3] *= al1;
        }

#pragma unroll
        for (int kc = 0; kc < 4; kc++) {
            uint32_t af[4];
            af[0] = pf0[2 * kc];
            af[1] = pf1[2 * kc];
            af[2] = pf0[2 * kc + 1];
            af[3] = pf1[2 * kc + 1];
#pragma unroll
            for (int jp = 0; jp < 4; jp++) {
                uint32_t q0, q1, q2, q3;
                const uint32_t va = vsb +
                    (uint32_t)((kc * 16 * HRA + jp * 16 + vlo) * 2);
                LDSM_T4(q0, q1, q2, q3, va);
                uint32_t bf0[2] = { q0, q1 };
                uint32_t bf1[2] = { q2, q3 };
                mma_f16(oacc[jp * 2],     af, bf0);
                mma_f16(oacc[jp * 2 + 1], af, bf1);
            }
        }
    }

    const float il0 = 1.f / l0;
    const float il1 = 1.f / l1;
    const size_t tok0 = (size_t)(brow + qb + r0);
    const size_t tok1 = (size_t)(brow + qb + r1);
#pragma unroll
    for (int jd = 0; jd < 8; jd++) {
        const int col = h * DH + jd * 8 + tg * 2;
        float2 x0 = *(const float2*)(X + tok0 * DD + col);
        float2 x1 = *(const float2*)(X + tok1 * DD + col);
        float2 o0 = make_float2(oacc[jd][0] * il0 + x0.x, oacc[jd][1] * il0 + x0.y);
        float2 o1 = make_float2(oacc[jd][2] * il1 + x1.x, oacc[jd][3] * il1 + x1.y);
        *(float2*)(X1 + tok0 * DD + col) = o0;
        *(float2*)(X1 + tok1 * DD + col) = o1;
    }
}

// ============================================================================
// LayerNorm over D=1280; emits fp16 for the FFN1 GEMM.
// ============================================================================
__global__ void __launch_bounds__(256)
ln_kernel(const float* __restrict__ X, const float* __restrict__ gam,
          const float* __restrict__ bet, __half* __restrict__ Y)
{
    const int row = blockIdx.x;
    const float* xr = X + (size_t)row * DD;
    float v[5];
    float sum = 0.f, sq = 0.f;
#pragma unroll
    for (int i = 0; i < 5; i++) {
        v[i] = xr[threadIdx.x + i * 256];
        sum += v[i];
        sq  += v[i] * v[i];
    }
#pragma unroll
    for (int off = 16; off; off >>= 1) {
        sum += __shfl_xor_sync(0xffffffffu, sum, off);
        sq  += __shfl_xor_sync(0xffffffffu, sq , off);
    }
    __shared__ float sS[8], sQ[8];
    const int w = threadIdx.x >> 5, lane = threadIdx.x & 31;
    if (lane == 0) { sS[w] = sum; sQ[w] = sq; }
    __syncthreads();
    if (threadIdx.x == 0) {
        float a = 0.f, q = 0.f;
#pragma unroll
        for (int i = 0; i < 8; i++) { a += sS[i]; q += sQ[i]; }
        sS[0] = a; sQ[0] = q;
    }
    __syncthreads();
    const float mu   = sS[0] * (1.0f / DD);
    const float var  = sQ[0] * (1.0f / DD) - mu * mu;
    const float rstd = rsqrtf(var + 1e-5f);
    __half* yr = Y + (size_t)row * DD;
#pragma unroll
    for (int i = 0; i < 5; i++) {
        int c = threadIdx.x + i * 256;
        yr[c] = __float2half_rn((v[i] - mu) * rstd * gam[c] + bet[c]);
    }
}

// ============================================================================
// launch (single stream — graph-capture safe)
// ============================================================================
extern "C" void kernel_launch(void* const* d_in, const int* in_sizes, int n_in,
                              void* d_out, int out_size)
{
    const float* x   = (const float*)d_in[0];
    const float* Wq  = (const float*)d_in[1];
    const float* Wk  = (const float*)d_in[2];
    const float* Wv  = (const float*)d_in[3];
    const float* lng = (const float*)d_in[4];
    const float* lnb = (const float*)d_in[5];
    const float* W1  = (const float*)d_in[6];
    const float* b1  = (const float*)d_in[7];
    const float* W2  = (const float*)d_in[8];
    const float* b2  = (const float*)d_in[9];
    float* out = (float*)d_out;

    __half *X16, *Wqkv, *W1t, *W2t, *QKV16, *H0, *H1;
    float *X1;
    cudaGetSymbolAddress((void**)&X16,   g_x16);
    cudaGetSymbolAddress((void**)&Wqkv,  g_Wqkv);
    cudaGetSymbolAddress((void**)&W1t,   g_W1t);
    cudaGetSymbolAddress((void**)&W2t,   g_W2t);
    cudaGetSymbolAddress((void**)&QKV16, g_QKV16);
    cudaGetSymbolAddress((void**)&X1,    g_x1);
    cudaGetSymbolAddress((void**)&H0,    g_h0);
    cudaGetSymbolAddress((void**)&H1,    g_h1);

    cudaFuncSetAttribute((const void*)gemm_f16<0,64>,  cudaFuncAttributeMaxDynamicSharedMemorySize, G16_SMEM(64));
    cudaFuncSetAttribute((const void*)gemm_f16<1,128>, cudaFuncAttributeMaxDynamicSharedMemorySize, G16_SMEM(128));
    cudaFuncSetAttribute((const void*)gemm_f16<2,128>, cudaFuncAttributeMaxDynamicSharedMemorySize, G16_SMEM(128));
    cudaFuncSetAttribute((const void*)attention_tc,    cudaFuncAttributeMaxDynamicSharedMemorySize, ATT_SMEM_BYTES);

    const dim3 blk(256);
    const dim3 tb(32, 8);

    // prep
    to_half<<<(MM*DD/4 + 255)/256, blk>>>(x, X16, MM*DD/4);
    thalf_qkv<<<dim3(DD/32, DD/32, 3), tb>>>(Wq, Wk, Wv, Wqkv);
    thalf2<<<dim3(DF/32, DD/32, 2), tb>>>(W1, W2, W1t, W2t);

    // QKV projection -> fp16
    gemm_f16<0,64><<<dim3(NQKV/128, MM/64), blk, G16_SMEM(64)>>>(
        X16, Wqkv, nullptr, QKV16, MM, NQKV, DD, nullptr, nullptr);

    // fused fp16 attention + residual
    attention_tc<<<dim3(SS/128, HH, BB), blk, ATT_SMEM_BYTES>>>(QKV16, x, X1);

    // layernorm -> fp16
    ln_kernel<<<MM, 256>>>(X1, lng, lnb, H0);

    // FFN
    gemm_f16<1,128><<<dim3(DF/128, MM/128), blk, G16_SMEM(128)>>>(
        H0, W1t, nullptr, H1, MM, DF, DD, b1, nullptr);
    gemm_f16<2,128><<<dim3(DD/128, MM/128), blk, G16_SMEM(128)>>>(
        H1, W2t, out, nullptr, MM, DD, DF, b2, X1);
}

// round 15
// speedup vs baseline: 1.0507x; 1.0030x over previous
#include <cuda_runtime.h>
#include <cuda_fp16.h>
#include <cstdint>

// ---------------- problem constants ----------------
#define BB 4
#define SS 1024
#define DD 1280
#define HH 20
#define DH 64
#define DF 5120
#define MM (BB*SS)          // 4096 rows
#define NQKV (3*DD)         // 3840

// ---------------- scratch (device globals) ----------------
__device__ __half g_x16  [(size_t)MM*DD];
__device__ __half g_Wqkv [(size_t)NQKV*DD];     // [N][K] fp16, Q rows pre-scaled
__device__ __half g_W1t  [(size_t)DF*DD];
__device__ __half g_W2t  [(size_t)DD*DF];
__device__ __half g_QKV16[(size_t)MM*NQKV];
__device__ float  g_x1   [MM*DD];
__device__ __half g_h0   [MM*DD];
__device__ __half g_h1   [(size_t)MM*DF];

__device__ __forceinline__ void mma_f16(float c[4], const uint32_t a[4], const uint32_t b[2]) {
    asm volatile(
        "mma.sync.aligned.m16n8k16.row.col.f32.f16.f16.f32 "
        "{%0,%1,%2,%3}, {%4,%5,%6,%7}, {%8,%9}, {%0,%1,%2,%3};\n"
        : "+f"(c[0]), "+f"(c[1]), "+f"(c[2]), "+f"(c[3])
        : "r"(a[0]), "r"(a[1]), "r"(a[2]), "r"(a[3]), "r"(b[0]), "r"(b[1]));
}

__device__ __forceinline__ uint32_t smem_u32(const void* p) {
    uint32_t a;
    asm("{ .reg .u64 t; cvta.to.shared.u64 t, %1; cvt.u32.u64 %0, t; }" : "=r"(a) : "l"(p));
    return a;
}

#define CP_ASYNC16(sm, gp) \
    asm volatile("cp.async.cg.shared.global [%0], [%1], 16;" :: "r"(sm), "l"(gp) : "memory")
#define CP_COMMIT() asm volatile("cp.async.commit_group;" ::: "memory")
#define CP_WAIT0()  asm volatile("cp.async.wait_group 0;" ::: "memory")

#define LDSM4(r0, r1, r2, r3, addr) \
    asm volatile("ldmatrix.sync.aligned.m8n8.x4.shared.b16 {%0,%1,%2,%3}, [%4];" \
                 : "=r"(r0), "=r"(r1), "=r"(r2), "=r"(r3) : "r"(addr))

#define LDSM_T4(r0, r1, r2, r3, addr) \
    asm volatile("ldmatrix.sync.aligned.m8n8.x4.trans.shared.b16 {%0,%1,%2,%3}, [%4];" \
                 : "=r"(r0), "=r"(r1), "=r"(r2), "=r"(r3) : "r"(addr))

// ============================================================================
// Prep kernels
// ============================================================================
__global__ void to_half(const float* __restrict__ in, __half* __restrict__ out, int n4)
{
    int i = blockIdx.x * 256 + threadIdx.x;
    if (i >= n4) return;
    float4 v = ((const float4*)in)[i];
    ((__half2*)out)[i * 2]     = __floats2half2_rn(v.x, v.y);
    ((__half2*)out)[i * 2 + 1] = __floats2half2_rn(v.z, v.w);
}

// fused Wq/Wk/Wv transpose+convert (z selects source; Q rows scaled 1/8)
__global__ void thalf_qkv(const float* __restrict__ Wq, const float* __restrict__ Wk,
                          const float* __restrict__ Wv, __half* __restrict__ dst)
{
    __shared__ float s[32][33];
    const int tx = threadIdx.x, ty = threadIdx.y;
    const int n0 = blockIdx.x * 32, k0 = blockIdx.y * 32;
    const int z  = blockIdx.z;
    const float* src = (z == 0) ? Wq : (z == 1) ? Wk : Wv;
    const float scale = (z == 0) ? 0.125f : 1.0f;
    __half* d = dst + (size_t)z * DD * DD;
#pragma unroll
    for (int i = 0; i < 4; i++)
        s[ty + i * 8][tx] = src[(size_t)(k0 + ty + i * 8) * DD + n0 + tx];
    __syncthreads();
#pragma unroll
    for (int i = 0; i < 4; i++)
        d[(size_t)(n0 + ty + i * 8) * DD + k0 + tx] =
            __float2half_rn(s[tx][ty + i * 8] * scale);
}

// combined W1 & W2 transpose+convert (validated round 13/14)
__global__ void thalf2(const float* __restrict__ W1, const float* __restrict__ W2,
                       __half* __restrict__ W1t, __half* __restrict__ W2t)
{
    __shared__ float s[32][33];
    const int tx = threadIdx.x, ty = threadIdx.y;
    const int z  = blockIdx.z;
    const float* src = z ? W2 : W1;
    __half* dst      = z ? W2t : W1t;
    const int K = z ? DF : DD;
    const int N = z ? DD : DF;
    const int n0 = (z ? blockIdx.y : blockIdx.x) * 32;
    const int k0 = (z ? blockIdx.x : blockIdx.y) * 32;
#pragma unroll
    for (int i = 0; i < 4; i++)
        s[ty + i * 8][tx] = src[(size_t)(k0 + ty + i * 8) * N + n0 + tx];
    __syncthreads();
#pragma unroll
    for (int i = 0; i < 4; i++)
        dst[(size_t)(n0 + ty + i * 8) * K + k0 + tx] =
            __float2half_rn(s[tx][ty + i * 8]);
}

// ============================================================================
// FP16 GEMM (m16n8k16, fp32 accum), cp.async 2-stage, ldmatrix fragment loads.
// MODE 0: C16 = half(AB); MODE 1: C16 = half(relu(AB+bias)); MODE 2: C = AB+bias+resid
// ============================================================================
#define HR 72
#define BH_ST (128*HR)
#define G16_SMEM(MT) (2*((MT)*HR + BH_ST)*2)

template <int MODE, int MTILE>
__global__ void __launch_bounds__(256, (MTILE == 128) ? 2 : 3)
gemm_f16(const __half* __restrict__ A, const __half* __restrict__ Bm,
         float* __restrict__ C, __half* __restrict__ C16, int M, int N, int K,
         const float* __restrict__ bias, const float* __restrict__ resid)
{
    constexpr int NI   = MTILE / 32;
    constexpr int PA   = MTILE / 32;
    constexpr int A_ST = MTILE * HR;
    constexpr int STG  = A_ST + BH_ST;

    extern __shared__ __half smh[];
    const uint32_t smb = smem_u32(smh);

    const int t    = threadIdx.x;
    const int lane = t & 31;
    const int w    = t >> 5;
    const int wm   = w & 1;
    const int wn   = w >> 1;
    const int g    = lane >> 2;
    const int tg   = lane & 3;
    const int m0   = blockIdx.y * MTILE;
    const int n0   = blockIdx.x * 128;

    const int ldr = t >> 3;
    const int ldc = (t & 7) * 8;
    const __half* Ag0 = A  + (size_t)(m0 + ldr) * K + ldc;
    const __half* Bg0 = Bm + (size_t)(n0 + ldr) * K + ldc;
    const uint32_t Asd = smb + (uint32_t)((ldr * HR + ldc) * 2);
    const uint32_t Bsd = smb + (uint32_t)((A_ST + ldr * HR + ldc) * 2);

    auto issue = [&](int kt, int buf) {
        const uint32_t bo = (uint32_t)(buf * STG * 2);
        const __half* Ag = Ag0 + kt * 64;
        const __half* Bg = Bg0 + kt * 64;
#pragma unroll
        for (int p = 0; p < PA; p++)
            CP_ASYNC16(Asd + bo + p * 32 * HR * 2, Ag + (size_t)p * 32 * K);
#pragma unroll
        for (int p = 0; p < 4; p++)
            CP_ASYNC16(Bsd + bo + p * 32 * HR * 2, Bg + (size_t)p * 32 * K);
        CP_COMMIT();
    };

    const int lm16 = lane & 15;
    const int lhi  = lane >> 4;
    const int lb8  = (lane >> 3) & 1;
    const int l8   = lane & 7;
    uint32_t aoff[NI], boff[2];
#pragma unroll
    for (int i = 0; i < NI; i++)
        aoff[i] = (uint32_t)(((wm * (MTILE / 2) + i * 16 + lm16) * HR + lhi * 8) * 2);
#pragma unroll
    for (int jp = 0; jp < 2; jp++)
        boff[jp] = (uint32_t)((A_ST + (wn * 32 + jp * 16 + lhi * 8 + l8) * HR + lb8 * 8) * 2);

    float acc[NI][4][4];
#pragma unroll
    for (int i = 0; i < NI; i++)
#pragma unroll
        for (int j = 0; j < 4; j++)
#pragma unroll
            for (int q = 0; q < 4; q++) acc[i][j][q] = 0.f;

    issue(0, 0);

    const int KT = K >> 6;
    for (int kt = 0; kt < KT; kt++) {
        CP_WAIT0();
        __syncthreads();
        if (kt + 1 < KT) issue(kt + 1, (kt + 1) & 1);

        const uint32_t bufb = smb + (uint32_t)((kt & 1) * STG * 2);
#pragma unroll
        for (int ks = 0; ks < 4; ks++) {
            const uint32_t cob = (uint32_t)(ks * 32);
            uint32_t af[NI][4], bf[4][2];
#pragma unroll
            for (int i = 0; i < NI; i++)
                LDSM4(af[i][0], af[i][1], af[i][2], af[i][3], bufb + aoff[i] + cob);
#pragma unroll
            for (int jp = 0; jp < 2; jp++)
                LDSM4(bf[2*jp][0], bf[2*jp][1], bf[2*jp+1][0], bf[2*jp+1][1],
                      bufb + boff[jp] + cob);
#pragma unroll
            for (int i = 0; i < NI; i++)
#pragma unroll
                for (int j = 0; j < 4; j++)
                    mma_f16(acc[i][j], af[i], bf[j]);
        }
        __syncthreads();
    }

    // ---------------- epilogue ----------------
    const int mrow = m0 + wm * (MTILE / 2);
    const int ncol = n0 + wn * 32;
#pragma unroll
    for (int j = 0; j < 4; j++) {
        const int colj = ncol + j * 8 + tg * 2;
        float2 bv = make_float2(0.f, 0.f);
        if (MODE == 1 || MODE == 2) bv = *(const float2*)(bias + colj);
#pragma unroll
        for (int i = 0; i < NI; i++) {
            const int r0 = mrow + i * 16 + g;
            float2 v0 = make_float2(acc[i][j][0], acc[i][j][1]);
            float2 v1 = make_float2(acc[i][j][2], acc[i][j][3]);
            if (MODE == 0) {
                *(__half2*)(C16 + (size_t)r0 * N + colj)       = __floats2half2_rn(v0.x, v0.y);
                *(__half2*)(C16 + (size_t)(r0 + 8) * N + colj) = __floats2half2_rn(v1.x, v1.y);
            } else if (MODE == 1) {
                __half2 h0 = __floats2half2_rn(fmaxf(v0.x + bv.x, 0.f), fmaxf(v0.y + bv.y, 0.f));
                __half2 h1 = __floats2half2_rn(fmaxf(v1.x + bv.x, 0.f), fmaxf(v1.y + bv.y, 0.f));
                *(__half2*)(C16 + (size_t)r0 * N + colj)       = h0;
                *(__half2*)(C16 + (size_t)(r0 + 8) * N + colj) = h1;
            } else {
                float2 r0v = *(const float2*)(resid + (size_t)r0 * N + colj);
                float2 r1v = *(const float2*)(resid + (size_t)(r0 + 8) * N + colj);
                v0.x += bv.x + r0v.x; v0.y += bv.y + r0v.y;
                v1.x += bv.x + r1v.x; v1.y += bv.y + r1v.y;
                *(float2*)(C + (size_t)r0 * N + colj)       = v0;
                *(float2*)(C + (size_t)(r0 + 8) * N + colj) = v1;
            }
        }
    }
}

// ============================================================================
// Flash attention v5: KV tile 128 (two 64-key halves per iteration; softmax
// order bit-identical to v4), halving sync/commit counts. qtile 128, 8 warps
// all-M, register softmax, P in registers, V via ldmatrix.trans.
// smem halves (stride 72): Q[128] | K[2][128] | V[2][128] = 92160 B, 2 CTAs/SM
// ============================================================================
#define HRA 72
#define KV_H2 (128*HRA)                 // 9216 halves per K/V buffer
#define OFF_KA (128*HRA)                // Q tile = 9216 halves
#define OFF_VA (OFF_KA + 2*KV_H2)
#define ATT_HALVES (OFF_VA + 2*KV_H2)   // 46080
#define ATT_SMEM_BYTES (ATT_HALVES*2)   // 92160

__global__ void __launch_bounds__(256, 2)
attention_tc(const __half* __restrict__ QKV, const float* __restrict__ X,
             float* __restrict__ X1)
{
    extern __shared__ __half smh[];
    const uint32_t smb = smem_u32(smh);

    const int t    = threadIdx.x;
    const int lane = t & 31;
    const int w    = t >> 5;
    const int g    = lane >> 2;
    const int tg   = lane & 3;

    const int qb   = blockIdx.x * 128;
    const int h    = blockIdx.y;
    const int b    = blockIdx.z;
    const int brow = b * SS;

    const __half* Qg = QKV + (size_t)(brow + qb) * NQKV + h * DH;
    const int ldr = t >> 3;
    const int ldc = (t & 7) * 8;

    // load 128 K rows + 128 V rows per call (4 passes of 32 rows each)
    auto issueKV = [&](int kb, int buf) {
        const __half* Kg = QKV + (size_t)(brow + kb) * NQKV + DD     + h * DH;
        const __half* Vg = QKV + (size_t)(brow + kb) * NQKV + 2 * DD + h * DH;
        const uint32_t kd = smb + (uint32_t)((OFF_KA + buf * KV_H2) * 2);
        const uint32_t vd = smb + (uint32_t)((OFF_VA + buf * KV_H2) * 2);
#pragma unroll
        for (int p = 0; p < 4; p++) {
            int r = ldr + p * 32;
            CP_ASYNC16(kd + (uint32_t)((r * HRA + ldc) * 2), Kg + (size_t)r * NQKV + ldc);
            CP_ASYNC16(vd + (uint32_t)((r * HRA + ldc) * 2), Vg + (size_t)r * NQKV + ldc);
        }
        CP_COMMIT();
    };

#pragma unroll
    for (int p = 0; p < 4; p++) {
        int e = p * 256 + t;
        int r = e >> 3, c8 = (e & 7) * 8;
        CP_ASYNC16(smb + (uint32_t)((r * HRA + c8) * 2), Qg + (size_t)r * NQKV + c8);
    }
    issueKV(0, 0);

    const int r0 = w * 16 + g;
    const int r1 = r0 + 8;
    float m0 = -1e30f, m1 = -1e30f, l0 = 0.f, l1 = 0.f;
    float oacc[8][4];
#pragma unroll
    for (int i = 0; i < 8; i++)
#pragma unroll
        for (int q = 0; q < 4; q++) oacc[i][q] = 0.f;

    const int lm16 = lane & 15;
    const int lhi  = lane >> 4;
    const int lb8  = (lane >> 3) & 1;
    const int l8   = lane & 7;
    const uint32_t qoff = (uint32_t)(((w * 16 + lm16) * HRA + lhi * 8) * 2);
    uint32_t koff[4];
#pragma unroll
    for (int jp = 0; jp < 4; jp++)
        koff[jp] = (uint32_t)(((jp * 16 + lhi * 8 + l8) * HRA + lb8 * 8) * 2);
    const int sel = lane >> 3;
    const int vlo = ((sel & 1) * 8 + l8) * HRA + (sel >> 1) * 8;

    for (int kt = 0; kt < SS / 128; kt++) {
        CP_WAIT0();
        __syncthreads();
        if (kt + 1 < SS / 128) issueKV((kt + 1) * 128, (kt + 1) & 1);

        const uint32_t ksb0 = smb + (uint32_t)((OFF_KA + (kt & 1) * KV_H2) * 2);
        const uint32_t vsb0 = smb + (uint32_t)((OFF_VA + (kt & 1) * KV_H2) * 2);

#pragma unroll
        for (int hh = 0; hh < 2; hh++) {
            const uint32_t ksb = ksb0 + (uint32_t)(hh * 64 * HRA * 2);
            const uint32_t vsb = vsb0 + (uint32_t)(hh * 64 * HRA * 2);

            // ---- S = Q K^T (64 keys) ----
            float sacc[8][4];
#pragma unroll
            for (int j = 0; j < 8; j++)
#pragma unroll
                for (int q = 0; q < 4; q++) sacc[j][q] = 0.f;

#pragma unroll
            for (int kc = 0; kc < 4; kc++) {
                const uint32_t cob = (uint32_t)(kc * 32);
                uint32_t af[4];
                LDSM4(af[0], af[1], af[2], af[3], smb + qoff + cob);
#pragma unroll
                for (int jp = 0; jp < 4; jp++) {
                    uint32_t k0r, k1r, k2r, k3r;
                    LDSM4(k0r, k1r, k2r, k3r, ksb + koff[jp] + cob);
                    uint32_t bf0[2] = { k0r, k1r };
                    uint32_t bf1[2] = { k2r, k3r };
                    mma_f16(sacc[2*jp],     af, bf0);
                    mma_f16(sacc[2*jp + 1], af, bf1);
                }
            }

            // ---- warp-local softmax ----
            float pm0 = -1e30f, pm1 = -1e30f;
#pragma unroll
            for (int j = 0; j < 8; j++) {
                pm0 = fmaxf(pm0, fmaxf(sacc[j][0], sacc[j][1]));
                pm1 = fmaxf(pm1, fmaxf(sacc[j][2], sacc[j][3]));
            }
            pm0 = fmaxf(pm0, __shfl_xor_sync(0xffffffffu, pm0, 1));
            pm0 = fmaxf(pm0, __shfl_xor_sync(0xffffffffu, pm0, 2));
            pm1 = fmaxf(pm1, __shfl_xor_sync(0xffffffffu, pm1, 1));
            pm1 = fmaxf(pm1, __shfl_xor_sync(0xffffffffu, pm1, 2));

            const float mn0 = fmaxf(m0, pm0);
            const float mn1 = fmaxf(m1, pm1);
            const float al0 = __expf(m0 - mn0);
            const float al1 = __expf(m1 - mn1);
            m0 = mn0; m1 = mn1;

            uint32_t pf0[8], pf1[8];
            float rs0 = 0.f, rs1 = 0.f;
#pragma unroll
            for (int j = 0; j < 8; j++) {
                float p00 = __expf(sacc[j][0] - mn0);
                float p01 = __expf(sacc[j][1] - mn0);
                float p10 = __expf(sacc[j][2] - mn1);
                float p11 = __expf(sacc[j][3] - mn1);
                rs0 += p00 + p01;
                rs1 += p10 + p11;
                __half2 h0 = __floats2half2_rn(p00, p01);
                __half2 h1 = __floats2half2_rn(p10, p11);
                pf0[j] = *(uint32_t*)&h0;
                pf1[j] = *(uint32_t*)&h1;
            }
            rs0 += __shfl_xor_sync(0xffffffffu, rs0, 1);
            rs0 += __shfl_xor_sync(0xffffffffu, rs0, 2);
            rs1 += __shfl_xor_sync(0xffffffffu, rs1, 1);
            rs1 += __shfl_xor_sync(0xffffffffu, rs1, 2);
            l0 = l0 * al0 + rs0;
            l1 = l1 * al1 + rs1;
#pragma unroll
            for (int i = 0; i < 8; i++) {
                oacc[i][0] *= al0; oacc[i][1] *= al0;
                oacc[i][2] *= al1; oacc[i][3] *= al1;
            }

            // ---- O += P @ V ----
#pragma unroll
            for (int kc = 0; kc < 4; kc++) {
                uint32_t af[4];
                af[0] = pf0[2 * kc];
                af[1] = pf1[2 * kc];
                af[2] = pf0[2 * kc + 1];
                af[3] = pf1[2 * kc + 1];
#pragma unroll
                for (int jp = 0; jp < 4; jp++) {
                    uint32_t q0, q1, q2, q3;
                    const uint32_t va = vsb +
                        (uint32_t)((kc * 16 * HRA + jp * 16 + vlo) * 2);
                    LDSM_T4(q0, q1, q2, q3, va);
                    uint32_t bf0[2] = { q0, q1 };
                    uint32_t bf1[2] = { q2, q3 };
                    mma_f16(oacc[jp * 2],     af, bf0);
                    mma_f16(oacc[jp * 2 + 1], af, bf1);
                }
            }
        }
    }

    const float il0 = 1.f / l0;
    const float il1 = 1.f / l1;
    const size_t tok0 = (size_t)(brow + qb + r0);
    const size_t tok1 = (size_t)(brow + qb + r1);
#pragma unroll
    for (int jd = 0; jd < 8; jd++) {
        const int col = h * DH + jd * 8 + tg * 2;
        float2 x0 = *(const float2*)(X + tok0 * DD + col);
        float2 x1 = *(const float2*)(X + tok1 * DD + col);
        float2 o0 = make_float2(oacc[jd][0] * il0 + x0.x, oacc[jd][1] * il0 + x0.y);
        float2 o1 = make_float2(oacc[jd][2] * il1 + x1.x, oacc[jd][3] * il1 + x1.y);
        *(float2*)(X1 + tok0 * DD + col) = o0;
        *(float2*)(X1 + tok1 * DD + col) = o1;
    }
}

// ============================================================================
// LayerNorm over D=1280; emits fp16 for the FFN1 GEMM.
// ============================================================================
__global__ void __launch_bounds__(256)
ln_kernel(const float* __restrict__ X, const float* __restrict__ gam,
          const float* __restrict__ bet, __half* __restrict__ Y)
{
    const int row = blockIdx.x;
    const float* xr = X + (size_t)row * DD;
    float v[5];
    float sum = 0.f, sq = 0.f;
#pragma unroll
    for (int i = 0; i < 5; i++) {
        v[i] = xr[threadIdx.x + i * 256];
        sum += v[i];
        sq  += v[i] * v[i];
    }
#pragma unroll
    for (int off = 16; off; off >>= 1) {
        sum += __shfl_xor_sync(0xffffffffu, sum, off);
        sq  += __shfl_xor_sync(0xffffffffu, sq , off);
    }
    __shared__ float sS[8], sQ[8];
    const int w = threadIdx.x >> 5, lane = threadIdx.x & 31;
    if (lane == 0) { sS[w] = sum; sQ[w] = sq; }
    __syncthreads();
    if (threadIdx.x == 0) {
        float a = 0.f, q = 0.f;
#pragma unroll
        for (int i = 0; i < 8; i++) { a += sS[i]; q += sQ[i]; }
        sS[0] = a; sQ[0] = q;
    }
    __syncthreads();
    const float mu   = sS[0] * (1.0f / DD);
    const float var  = sQ[0] * (1.0f / DD) - mu * mu;
    const float rstd = rsqrtf(var + 1e-5f);
    __half* yr = Y + (size_t)row * DD;
#pragma unroll
    for (int i = 0; i < 5; i++) {
        int c = threadIdx.x + i * 256;
        yr[c] = __float2half_rn((v[i] - mu) * rstd * gam[c] + bet[c]);
    }
}

// ============================================================================
// launch (single stream — graph-capture safe)
// ============================================================================
extern "C" void kernel_launch(void* const* d_in, const int* in_sizes, int n_in,
                              void* d_out, int out_size)
{
    const float* x   = (const float*)d_in[0];
    const float* Wq  = (const float*)d_in[1];
    const float* Wk  = (const float*)d_in[2];
    const float* Wv  = (const float*)d_in[3];
    const float* lng = (const float*)d_in[4];
    const float* lnb = (const float*)d_in[5];
    const float* W1  = (const float*)d_in[6];
    const float* b1  = (const float*)d_in[7];
    const float* W2  = (const float*)d_in[8];
    const float* b2  = (const float*)d_in[9];
    float* out = (float*)d_out;

    __half *X16, *Wqkv, *W1t, *W2t, *QKV16, *H0, *H1;
    float *X1;
    cudaGetSymbolAddress((void**)&X16,   g_x16);
    cudaGetSymbolAddress((void**)&Wqkv,  g_Wqkv);
    cudaGetSymbolAddress((void**)&W1t,   g_W1t);
    cudaGetSymbolAddress((void**)&W2t,   g_W2t);
    cudaGetSymbolAddress((void**)&QKV16, g_QKV16);
    cudaGetSymbolAddress((void**)&X1,    g_x1);
    cudaGetSymbolAddress((void**)&H0,    g_h0);
    cudaGetSymbolAddress((void**)&H1,    g_h1);

    cudaFuncSetAttribute((const void*)gemm_f16<0,64>,  cudaFuncAttributeMaxDynamicSharedMemorySize, G16_SMEM(64));
    cudaFuncSetAttribute((const void*)gemm_f16<1,128>, cudaFuncAttributeMaxDynamicSharedMemorySize, G16_SMEM(128));
    cudaFuncSetAttribute((const void*)gemm_f16<2,128>, cudaFuncAttributeMaxDynamicSharedMemorySize, G16_SMEM(128));
    cudaFuncSetAttribute((const void*)attention_tc,    cudaFuncAttributeMaxDynamicSharedMemorySize, ATT_SMEM_BYTES);

    const dim3 blk(256);
    const dim3 tb(32, 8);

    // prep
    to_half<<<(MM*DD/4 + 255)/256, blk>>>(x, X16, MM*DD/4);
    thalf_qkv<<<dim3(DD/32, DD/32, 3), tb>>>(Wq, Wk, Wv, Wqkv);
    thalf2<<<dim3(DF/32, DD/32, 2), tb>>>(W1, W2, W1t, W2t);

    // QKV projection -> fp16
    gemm_f16<0,64><<<dim3(NQKV/128, MM/64), blk, G16_SMEM(64)>>>(
        X16, Wqkv, nullptr, QKV16, MM, NQKV, DD, nullptr, nullptr);

    // fused fp16 attention + residual (KV tile 128)
    attention_tc<<<dim3(SS/128, HH, BB), blk, ATT_SMEM_BYTES>>>(QKV16, x, X1);

    // layernorm -> fp16
    ln_kernel<<<MM, 256>>>(X1, lng, lnb, H0);

    // FFN
    gemm_f16<1,128><<<dim3(DF/128, MM/128), blk, G16_SMEM(128)>>>(
        H0, W1t, nullptr, H1, MM, DF, DD, b1, nullptr);
    gemm_f16<2,128><<<dim3(DD/128, MM/128), blk, G16_SMEM(128)>>>(
        H1, W2t, out, nullptr, MM, DD, DF, b2, X1);
}

// round 16
// speedup vs baseline: 1.0534x; 1.0026x over previous
#include <cuda_runtime.h>
#include <cuda_fp16.h>
#include <cstdint>

// ---------------- problem constants ----------------
#define BB 4
#define SS 1024
#define DD 1280
#define HH 20
#define DH 64
#define DF 5120
#define MM (BB*SS)          // 4096 rows
#define NQKV (3*DD)         // 3840

// ---------------- scratch (device globals) ----------------
__device__ __half g_x16  [(size_t)MM*DD];
__device__ __half g_Wqkv [(size_t)NQKV*DD];     // [N][K] fp16; Q rows scaled 0.125*log2e
__device__ __half g_W1t  [(size_t)DF*DD];
__device__ __half g_W2t  [(size_t)DD*DF];
__device__ __half g_QKV16[(size_t)MM*NQKV];
__device__ float  g_x1   [MM*DD];
__device__ __half g_h0   [MM*DD];
__device__ __half g_h1   [(size_t)MM*DF];

__device__ __forceinline__ void mma_f16(float c[4], const uint32_t a[4], const uint32_t b[2]) {
    asm volatile(
        "mma.sync.aligned.m16n8k16.row.col.f32.f16.f16.f32 "
        "{%0,%1,%2,%3}, {%4,%5,%6,%7}, {%8,%9}, {%0,%1,%2,%3};\n"
        : "+f"(c[0]), "+f"(c[1]), "+f"(c[2]), "+f"(c[3])
        : "r"(a[0]), "r"(a[1]), "r"(a[2]), "r"(a[3]), "r"(b[0]), "r"(b[1]));
}

__device__ __forceinline__ uint32_t smem_u32(const void* p) {
    uint32_t a;
    asm("{ .reg .u64 t; cvta.to.shared.u64 t, %1; cvt.u32.u64 %0, t; }" : "=r"(a) : "l"(p));
    return a;
}

#define CP_ASYNC16(sm, gp) \
    asm volatile("cp.async.cg.shared.global [%0], [%1], 16;" :: "r"(sm), "l"(gp) : "memory")
#define CP_COMMIT() asm volatile("cp.async.commit_group;" ::: "memory")
#define CP_WAIT0()  asm volatile("cp.async.wait_group 0;" ::: "memory")

#define LDSM4(r0, r1, r2, r3, addr) \
    asm volatile("ldmatrix.sync.aligned.m8n8.x4.shared.b16 {%0,%1,%2,%3}, [%4];" \
                 : "=r"(r0), "=r"(r1), "=r"(r2), "=r"(r3) : "r"(addr))

#define LDSM_T4(r0, r1, r2, r3, addr) \
    asm volatile("ldmatrix.sync.aligned.m8n8.x4.trans.shared.b16 {%0,%1,%2,%3}, [%4];" \
                 : "=r"(r0), "=r"(r1), "=r"(r2), "=r"(r3) : "r"(addr))

// ============================================================================
// Prep kernels
// ============================================================================
__global__ void to_half(const float* __restrict__ in, __half* __restrict__ out, int n4)
{
    int i = blockIdx.x * 256 + threadIdx.x;
    if (i >= n4) return;
    float4 v = ((const float4*)in)[i];
    ((__half2*)out)[i * 2]     = __floats2half2_rn(v.x, v.y);
    ((__half2*)out)[i * 2 + 1] = __floats2half2_rn(v.z, v.w);
}

// fused Wq/Wk/Wv transpose+convert; Q rows pre-scaled by 0.125*log2(e) so the
// attention softmax can use exp2 directly.
__global__ void thalf_qkv(const float* __restrict__ Wq, const float* __restrict__ Wk,
                          const float* __restrict__ Wv, __half* __restrict__ dst)
{
    __shared__ float s[32][33];
    const int tx = threadIdx.x, ty = threadIdx.y;
    const int n0 = blockIdx.x * 32, k0 = blockIdx.y * 32;
    const int z  = blockIdx.z;
    const float* src = (z == 0) ? Wq : (z == 1) ? Wk : Wv;
    const float scale = (z == 0) ? 0.125f * 1.44269504f : 1.0f;
    __half* d = dst + (size_t)z * DD * DD;
#pragma unroll
    for (int i = 0; i < 4; i++)
        s[ty + i * 8][tx] = src[(size_t)(k0 + ty + i * 8) * DD + n0 + tx];
    __syncthreads();
#pragma unroll
    for (int i = 0; i < 4; i++)
        d[(size_t)(n0 + ty + i * 8) * DD + k0 + tx] =
            __float2half_rn(s[tx][ty + i * 8] * scale);
}

// combined W1 & W2 transpose+convert (validated round 13-15)
__global__ void thalf2(const float* __restrict__ W1, const float* __restrict__ W2,
                       __half* __restrict__ W1t, __half* __restrict__ W2t)
{
    __shared__ float s[32][33];
    const int tx = threadIdx.x, ty = threadIdx.y;
    const int z  = blockIdx.z;
    const float* src = z ? W2 : W1;
    __half* dst      = z ? W2t : W1t;
    const int K = z ? DF : DD;
    const int N = z ? DD : DF;
    const int n0 = (z ? blockIdx.y : blockIdx.x) * 32;
    const int k0 = (z ? blockIdx.x : blockIdx.y) * 32;
#pragma unroll
    for (int i = 0; i < 4; i++)
        s[ty + i * 8][tx] = src[(size_t)(k0 + ty + i * 8) * N + n0 + tx];
    __syncthreads();
#pragma unroll
    for (int i = 0; i < 4; i++)
        dst[(size_t)(n0 + ty + i * 8) * K + k0 + tx] =
            __float2half_rn(s[tx][ty + i * 8]);
}

// ============================================================================
// FP16 GEMM (m16n8k16, fp32 accum), cp.async 2-stage, ldmatrix fragment loads.
// MODE 0: C16 = half(AB); MODE 1: C16 = half(relu(AB+bias)); MODE 2: C = AB+bias+resid
// ============================================================================
#define HR 72
#define BH_ST (128*HR)
#define G16_SMEM(MT) (2*((MT)*HR + BH_ST)*2)

template <int MODE, int MTILE>
__global__ void __launch_bounds__(256, (MTILE == 128) ? 2 : 3)
gemm_f16(const __half* __restrict__ A, const __half* __restrict__ Bm,
         float* __restrict__ C, __half* __restrict__ C16, int M, int N, int K,
         const float* __restrict__ bias, const float* __restrict__ resid)
{
    constexpr int NI   = MTILE / 32;
    constexpr int PA   = MTILE / 32;
    constexpr int A_ST = MTILE * HR;
    constexpr int STG  = A_ST + BH_ST;

    extern __shared__ __half smh[];
    const uint32_t smb = smem_u32(smh);

    const int t    = threadIdx.x;
    const int lane = t & 31;
    const int w    = t >> 5;
    const int wm   = w & 1;
    const int wn   = w >> 1;
    const int g    = lane >> 2;
    const int tg   = lane & 3;
    const int m0   = blockIdx.y * MTILE;
    const int n0   = blockIdx.x * 128;

    const int ldr = t >> 3;
    const int ldc = (t & 7) * 8;
    const __half* Ag0 = A  + (size_t)(m0 + ldr) * K + ldc;
    const __half* Bg0 = Bm + (size_t)(n0 + ldr) * K + ldc;
    const uint32_t Asd = smb + (uint32_t)((ldr * HR + ldc) * 2);
    const uint32_t Bsd = smb + (uint32_t)((A_ST + ldr * HR + ldc) * 2);

    auto issue = [&](int kt, int buf) {
        const uint32_t bo = (uint32_t)(buf * STG * 2);
        const __half* Ag = Ag0 + kt * 64;
        const __half* Bg = Bg0 + kt * 64;
#pragma unroll
        for (int p = 0; p < PA; p++)
            CP_ASYNC16(Asd + bo + p * 32 * HR * 2, Ag + (size_t)p * 32 * K);
#pragma unroll
        for (int p = 0; p < 4; p++)
            CP_ASYNC16(Bsd + bo + p * 32 * HR * 2, Bg + (size_t)p * 32 * K);
        CP_COMMIT();
    };

    const int lm16 = lane & 15;
    const int lhi  = lane >> 4;
    const int lb8  = (lane >> 3) & 1;
    const int l8   = lane & 7;
    uint32_t aoff[NI], boff[2];
#pragma unroll
    for (int i = 0; i < NI; i++)
        aoff[i] = (uint32_t)(((wm * (MTILE / 2) + i * 16 + lm16) * HR + lhi * 8) * 2);
#pragma unroll
    for (int jp = 0; jp < 2; jp++)
        boff[jp] = (uint32_t)((A_ST + (wn * 32 + jp * 16 + lhi * 8 + l8) * HR + lb8 * 8) * 2);

    float acc[NI][4][4];
#pragma unroll
    for (int i = 0; i < NI; i++)
#pragma unroll
        for (int j = 0; j < 4; j++)
#pragma unroll
            for (int q = 0; q < 4; q++) acc[i][j][q] = 0.f;

    issue(0, 0);

    const int KT = K >> 6;
    for (int kt = 0; kt < KT; kt++) {
        CP_WAIT0();
        __syncthreads();
        if (kt + 1 < KT) issue(kt + 1, (kt + 1) & 1);

        const uint32_t bufb = smb + (uint32_t)((kt & 1) * STG * 2);
#pragma unroll
        for (int ks = 0; ks < 4; ks++) {
            const uint32_t cob = (uint32_t)(ks * 32);
            uint32_t af[NI][4], bf[4][2];
#pragma unroll
            for (int i = 0; i < NI; i++)
                LDSM4(af[i][0], af[i][1], af[i][2], af[i][3], bufb + aoff[i] + cob);
#pragma unroll
            for (int jp = 0; jp < 2; jp++)
                LDSM4(bf[2*jp][0], bf[2*jp][1], bf[2*jp+1][0], bf[2*jp+1][1],
                      bufb + boff[jp] + cob);
#pragma unroll
            for (int i = 0; i < NI; i++)
#pragma unroll
                for (int j = 0; j < 4; j++)
                    mma_f16(acc[i][j], af[i], bf[j]);
        }
        __syncthreads();
    }

    // ---------------- epilogue ----------------
    const int mrow = m0 + wm * (MTILE / 2);
    const int ncol = n0 + wn * 32;
#pragma unroll
    for (int j = 0; j < 4; j++) {
        const int colj = ncol + j * 8 + tg * 2;
        float2 bv = make_float2(0.f, 0.f);
        if (MODE == 1 || MODE == 2) bv = *(const float2*)(bias + colj);
#pragma unroll
        for (int i = 0; i < NI; i++) {
            const int r0 = mrow + i * 16 + g;
            float2 v0 = make_float2(acc[i][j][0], acc[i][j][1]);
            float2 v1 = make_float2(acc[i][j][2], acc[i][j][3]);
            if (MODE == 0) {
                *(__half2*)(C16 + (size_t)r0 * N + colj)       = __floats2half2_rn(v0.x, v0.y);
                *(__half2*)(C16 + (size_t)(r0 + 8) * N + colj) = __floats2half2_rn(v1.x, v1.y);
            } else if (MODE == 1) {
                __half2 h0 = __floats2half2_rn(fmaxf(v0.x + bv.x, 0.f), fmaxf(v0.y + bv.y, 0.f));
                __half2 h1 = __floats2half2_rn(fmaxf(v1.x + bv.x, 0.f), fmaxf(v1.y + bv.y, 0.f));
                *(__half2*)(C16 + (size_t)r0 * N + colj)       = h0;
                *(__half2*)(C16 + (size_t)(r0 + 8) * N + colj) = h1;
            } else {
                float2 r0v = *(const float2*)(resid + (size_t)r0 * N + colj);
                float2 r1v = *(const float2*)(resid + (size_t)(r0 + 8) * N + colj);
                v0.x += bv.x + r0v.x; v0.y += bv.y + r0v.y;
                v1.x += bv.x + r1v.x; v1.y += bv.y + r1v.y;
                *(float2*)(C + (size_t)r0 * N + colj)       = v0;
                *(float2*)(C + (size_t)(r0 + 8) * N + colj) = v1;
            }
        }
    }
}

// ============================================================================
// Flash attention v5 (KV tile 128, validated round 15) with exp2 softmax
// (log2e folded into Q weights). qtile 128, 8 warps all-M, register softmax.
// ============================================================================
#define HRA 72
#define KV_H2 (128*HRA)
#define OFF_KA (128*HRA)
#define OFF_VA (OFF_KA + 2*KV_H2)
#define ATT_HALVES (OFF_VA + 2*KV_H2)
#define ATT_SMEM_BYTES (ATT_HALVES*2)

__global__ void __launch_bounds__(256, 2)
attention_tc(const __half* __restrict__ QKV, const float* __restrict__ X,
             float* __restrict__ X1)
{
    extern __shared__ __half smh[];
    const uint32_t smb = smem_u32(smh);

    const int t    = threadIdx.x;
    const int lane = t & 31;
    const int w    = t >> 5;
    const int g    = lane >> 2;
    const int tg   = lane & 3;

    const int qb   = blockIdx.x * 128;
    const int h    = blockIdx.y;
    const int b    = blockIdx.z;
    const int brow = b * SS;

    const __half* Qg = QKV + (size_t)(brow + qb) * NQKV + h * DH;
    const int ldr = t >> 3;
    const int ldc = (t & 7) * 8;

    auto issueKV = [&](int kb, int buf) {
        const __half* Kg = QKV + (size_t)(brow + kb) * NQKV + DD     + h * DH;
        const __half* Vg = QKV + (size_t)(brow + kb) * NQKV + 2 * DD + h * DH;
        const uint32_t kd = smb + (uint32_t)((OFF_KA + buf * KV_H2) * 2);
        const uint32_t vd = smb + (uint32_t)((OFF_VA + buf * KV_H2) * 2);
#pragma unroll
        for (int p = 0; p < 4; p++) {
            int r = ldr + p * 32;
            CP_ASYNC16(kd + (uint32_t)((r * HRA + ldc) * 2), Kg + (size_t)r * NQKV + ldc);
            CP_ASYNC16(vd + (uint32_t)((r * HRA + ldc) * 2), Vg + (size_t)r * NQKV + ldc);
        }
        CP_COMMIT();
    };

#pragma unroll
    for (int p = 0; p < 4; p++) {
        int e = p * 256 + t;
        int r = e >> 3, c8 = (e & 7) * 8;
        CP_ASYNC16(smb + (uint32_t)((r * HRA + c8) * 2), Qg + (size_t)r * NQKV + c8);
    }
    issueKV(0, 0);

    const int r0 = w * 16 + g;
    const int r1 = r0 + 8;
    float m0 = -1e30f, m1 = -1e30f, l0 = 0.f, l1 = 0.f;
    float oacc[8][4];
#pragma unroll
    for (int i = 0; i < 8; i++)
#pragma unroll
        for (int q = 0; q < 4; q++) oacc[i][q] = 0.f;

    const int lm16 = lane & 15;
    const int lhi  = lane >> 4;
    const int lb8  = (lane >> 3) & 1;
    const int l8   = lane & 7;
    const uint32_t qoff = (uint32_t)(((w * 16 + lm16) * HRA + lhi * 8) * 2);
    uint32_t koff[4];
#pragma unroll
    for (int jp = 0; jp < 4; jp++)
        koff[jp] = (uint32_t)(((jp * 16 + lhi * 8 + l8) * HRA + lb8 * 8) * 2);
    const int sel = lane >> 3;
    const int vlo = ((sel & 1) * 8 + l8) * HRA + (sel >> 1) * 8;

    for (int kt = 0; kt < SS / 128; kt++) {
        CP_WAIT0();
        __syncthreads();
        if (kt + 1 < SS / 128) issueKV((kt + 1) * 128, (kt + 1) & 1);

        const uint32_t ksb0 = smb + (uint32_t)((OFF_KA + (kt & 1) * KV_H2) * 2);
        const uint32_t vsb0 = smb + (uint32_t)((OFF_VA + (kt & 1) * KV_H2) * 2);

#pragma unroll
        for (int hh = 0; hh < 2; hh++) {
            const uint32_t ksb = ksb0 + (uint32_t)(hh * 64 * HRA * 2);
            const uint32_t vsb = vsb0 + (uint32_t)(hh * 64 * HRA * 2);

            // ---- S = Q K^T (64 keys; S already in log2 scale) ----
            float sacc[8][4];
#pragma unroll
            for (int j = 0; j < 8; j++)
#pragma unroll
                for (int q = 0; q < 4; q++) sacc[j][q] = 0.f;

#pragma unroll
            for (int kc = 0; kc < 4; kc++) {
                const uint32_t cob = (uint32_t)(kc * 32);
                uint32_t af[4];
                LDSM4(af[0], af[1], af[2], af[3], smb + qoff + cob);
#pragma unroll
                for (int jp = 0; jp < 4; jp++) {
                    uint32_t k0r, k1r, k2r, k3r;
                    LDSM4(k0r, k1r, k2r, k3r, ksb + koff[jp] + cob);
                    uint32_t bf0[2] = { k0r, k1r };
                    uint32_t bf1[2] = { k2r, k3r };
                    mma_f16(sacc[2*jp],     af, bf0);
                    mma_f16(sacc[2*jp + 1], af, bf1);
                }
            }

            // ---- warp-local softmax (exp2 domain) ----
            float pm0 = -1e30f, pm1 = -1e30f;
#pragma unroll
            for (int j = 0; j < 8; j++) {
                pm0 = fmaxf(pm0, fmaxf(sacc[j][0], sacc[j][1]));
                pm1 = fmaxf(pm1, fmaxf(sacc[j][2], sacc[j][3]));
            }
            pm0 = fmaxf(pm0, __shfl_xor_sync(0xffffffffu, pm0, 1));
            pm0 = fmaxf(pm0, __shfl_xor_sync(0xffffffffu, pm0, 2));
            pm1 = fmaxf(pm1, __shfl_xor_sync(0xffffffffu, pm1, 1));
            pm1 = fmaxf(pm1, __shfl_xor_sync(0xffffffffu, pm1, 2));

            const float mn0 = fmaxf(m0, pm0);
            const float mn1 = fmaxf(m1, pm1);
            const float al0 = exp2f(m0 - mn0);
            const float al1 = exp2f(m1 - mn1);
            m0 = mn0; m1 = mn1;

            uint32_t pf0[8], pf1[8];
            float rs0 = 0.f, rs1 = 0.f;
#pragma unroll
            for (int j = 0; j < 8; j++) {
                float p00 = exp2f(sacc[j][0] - mn0);
                float p01 = exp2f(sacc[j][1] - mn0);
                float p10 = exp2f(sacc[j][2] - mn1);
                float p11 = exp2f(sacc[j][3] - mn1);
                rs0 += p00 + p01;
                rs1 += p10 + p11;
                __half2 h0 = __floats2half2_rn(p00, p01);
                __half2 h1 = __floats2half2_rn(p10, p11);
                pf0[j] = *(uint32_t*)&h0;
                pf1[j] = *(uint32_t*)&h1;
            }
            rs0 += __shfl_xor_sync(0xffffffffu, rs0, 1);
            rs0 += __shfl_xor_sync(0xffffffffu, rs0, 2);
            rs1 += __shfl_xor_sync(0xffffffffu, rs1, 1);
            rs1 += __shfl_xor_sync(0xffffffffu, rs1, 2);
            l0 = l0 * al0 + rs0;
            l1 = l1 * al1 + rs1;
#pragma unroll
            for (int i = 0; i < 8; i++) {
                oacc[i][0] *= al0; oacc[i][1] *= al0;
                oacc[i][2] *= al1; oacc[i][3] *= al1;
            }

            // ---- O += P @ V ----
#pragma unroll
            for (int kc = 0; kc < 4; kc++) {
                uint32_t af[4];
                af[0] = pf0[2 * kc];
                af[1] = pf1[2 * kc];
                af[2] = pf0[2 * kc + 1];
                af[3] = pf1[2 * kc + 1];
#pragma unroll
                for (int jp = 0; jp < 4; jp++) {
                    uint32_t q0, q1, q2, q3;
                    const uint32_t va = vsb +
                        (uint32_t)((kc * 16 * HRA + jp * 16 + vlo) * 2);
                    LDSM_T4(q0, q1, q2, q3, va);
                    uint32_t bf0[2] = { q0, q1 };
                    uint32_t bf1[2] = { q2, q3 };
                    mma_f16(oacc[jp * 2],     af, bf0);
                    mma_f16(oacc[jp * 2 + 1], af, bf1);
                }
            }
        }
    }

    const float il0 = 1.f / l0;
    const float il1 = 1.f / l1;
    const size_t tok0 = (size_t)(brow + qb + r0);
    const size_t tok1 = (size_t)(brow + qb + r1);
#pragma unroll
    for (int jd = 0; jd < 8; jd++) {
        const int col = h * DH + jd * 8 + tg * 2;
        float2 x0 = *(const float2*)(X + tok0 * DD + col);
        float2 x1 = *(const float2*)(X + tok1 * DD + col);
        float2 o0 = make_float2(oacc[jd][0] * il0 + x0.x, oacc[jd][1] * il0 + x0.y);
        float2 o1 = make_float2(oacc[jd][2] * il1 + x1.x, oacc[jd][3] * il1 + x1.y);
        *(float2*)(X1 + tok0 * DD + col) = o0;
        *(float2*)(X1 + tok1 * DD + col) = o1;
    }
}

// ============================================================================
// LayerNorm over D=1280; float4 loads, 320 threads (1 float4/thread/row),
// emits fp16 for the FFN1 GEMM.
// ============================================================================
__global__ void __launch_bounds__(320)
ln_kernel(const float* __restrict__ X, const float* __restrict__ gam,
          const float* __restrict__ bet, __half* __restrict__ Y)
{
    const int row = blockIdx.x;
    const int t   = threadIdx.x;
    const float4 v = *(const float4*)(X + (size_t)row * DD + t * 4);
    float sum = v.x + v.y + v.z + v.w;
    float sq  = v.x*v.x + v.y*v.y + v.z*v.z + v.w*v.w;
#pragma unroll
    for (int off = 16; off; off >>= 1) {
        sum += __shfl_xor_sync(0xffffffffu, sum, off);
        sq  += __shfl_xor_sync(0xffffffffu, sq , off);
    }
    __shared__ float sS[10], sQ[10];
    const int w = t >> 5, lane = t & 31;
    if (lane == 0) { sS[w] = sum; sQ[w] = sq; }
    __syncthreads();
    if (t == 0) {
        float a = 0.f, q = 0.f;
#pragma unroll
        for (int i = 0; i < 10; i++) { a += sS[i]; q += sQ[i]; }
        sS[0] = a; sQ[0] = q;
    }
    __syncthreads();
    const float mu   = sS[0] * (1.0f / DD);
    const float var  = sQ[0] * (1.0f / DD) - mu * mu;
    const float rstd = rsqrtf(var + 1e-5f);
    const float4 gv = *(const float4*)(gam + t * 4);
    const float4 bv = *(const float4*)(bet + t * 4);
    __half2 h0 = __floats2half2_rn((v.x - mu) * rstd * gv.x + bv.x,
                                   (v.y - mu) * rstd * gv.y + bv.y);
    __half2 h1 = __floats2half2_rn((v.z - mu) * rstd * gv.z + bv.z,
                                   (v.w - mu) * rstd * gv.w + bv.w);
    __half2* yp = (__half2*)(Y + (size_t)row * DD + t * 4);
    yp[0] = h0;
    yp[1] = h1;
}

// ============================================================================
// launch (single stream — graph-capture safe)
// ============================================================================
extern "C" void kernel_launch(void* const* d_in, const int* in_sizes, int n_in,
                              void* d_out, int out_size)
{
    const float* x   = (const float*)d_in[0];
    const float* Wq  = (const float*)d_in[1];
    const float* Wk  = (const float*)d_in[2];
    const float* Wv  = (const float*)d_in[3];
    const float* lng = (const float*)d_in[4];
    const float* lnb = (const float*)d_in[5];
    const float* W1  = (const float*)d_in[6];
    const float* b1  = (const float*)d_in[7];
    const float* W2  = (const float*)d_in[8];
    const float* b2  = (const float*)d_in[9];
    float* out = (float*)d_out;

    __half *X16, *Wqkv, *W1t, *W2t, *QKV16, *H0, *H1;
    float *X1;
    cudaGetSymbolAddress((void**)&X16,   g_x16);
    cudaGetSymbolAddress((void**)&Wqkv,  g_Wqkv);
    cudaGetSymbolAddress((void**)&W1t,   g_W1t);
    cudaGetSymbolAddress((void**)&W2t,   g_W2t);
    cudaGetSymbolAddress((void**)&QKV16, g_QKV16);
    cudaGetSymbolAddress((void**)&X1,    g_x1);
    cudaGetSymbolAddress((void**)&H0,    g_h0);
    cudaGetSymbolAddress((void**)&H1,    g_h1);

    cudaFuncSetAttribute((const void*)gemm_f16<0,64>,  cudaFuncAttributeMaxDynamicSharedMemorySize, G16_SMEM(64));
    cudaFuncSetAttribute((const void*)gemm_f16<1,128>, cudaFuncAttributeMaxDynamicSharedMemorySize, G16_SMEM(128));
    cudaFuncSetAttribute((const void*)gemm_f16<2,128>, cudaFuncAttributeMaxDynamicSharedMemorySize, G16_SMEM(128));
    cudaFuncSetAttribute((const void*)attention_tc,    cudaFuncAttributeMaxDynamicSharedMemorySize, ATT_SMEM_BYTES);

    const dim3 blk(256);
    const dim3 tb(32, 8);

    // prep
    to_half<<<(MM*DD/4 + 255)/256, blk>>>(x, X16, MM*DD/4);
    thalf_qkv<<<dim3(DD/32, DD/32, 3), tb>>>(Wq, Wk, Wv, Wqkv);
    thalf2<<<dim3(DF/32, DD/32, 2), tb>>>(W1, W2, W1t, W2t);

    // QKV projection -> fp16 (Q scaled by 0.125*log2e)
    gemm_f16<0,64><<<dim3(NQKV/128, MM/64), blk, G16_SMEM(64)>>>(
        X16, Wqkv, nullptr, QKV16, MM, NQKV, DD, nullptr, nullptr);

    // fused fp16 attention + residual (exp2 softmax)
    attention_tc<<<dim3(SS/128, HH, BB), blk, ATT_SMEM_BYTES>>>(QKV16, x, X1);

    // layernorm -> fp16 (vectorized)
    ln_kernel<<<MM, 320>>>(X1, lng, lnb, H0);

    // FFN
    gemm_f16<1,128><<<dim3(DF/128, MM/128), blk, G16_SMEM(128)>>>(
        H0, W1t, nullptr, H1, MM, DF, DD, b1, nullptr);
    gemm_f16<2,128><<<dim3(DD/128, MM/128), blk, G16_SMEM(128)>>>(
        H1, W2t, out, nullptr, MM, DD, DF, b2, X1);
}